// round 1
// baseline (speedup 1.0000x reference)
#include <cuda_runtime.h>
#include <math.h>

#define BATCH 32
#define SEQ   4096
#define UNITS 1024
#define M_TOTAL (BATCH * SEQ)      // 131072
#define NBLK  8                    // 8 column tiles of 128 over N=1024

// Scratch (device globals — no allocations allowed)
__device__ float g_wsb[BATCH * UNITS];                 // ws + W_b + U_b
__device__ float g_score_part[(size_t)M_TOTAL * NBLK]; // partial scores per N-tile
__device__ float g_ctx_part[BATCH * 8 * UNITS];        // partial contexts per S-split

// ---------------------------------------------------------------------------
// Kernel 1: wsb[b,v] = sum_k s_prev[b,k] * W_w[k,v] + W_b[v] + U_b[v]
// grid = BATCH, block = UNITS
// ---------------------------------------------------------------------------
__global__ void ws_kernel(const float* __restrict__ s_prev,
                          const float* __restrict__ W_w,
                          const float* __restrict__ W_b,
                          const float* __restrict__ U_b) {
    __shared__ float srow[UNITS];
    int b = blockIdx.x;
    int v = threadIdx.x;
    srow[v] = s_prev[b * UNITS + v];
    __syncthreads();
    float a0 = 0.f, a1 = 0.f, a2 = 0.f, a3 = 0.f;
    #pragma unroll 4
    for (int k = 0; k < UNITS; k += 4) {
        a0 += srow[k + 0] * W_w[(size_t)(k + 0) * UNITS + v];
        a1 += srow[k + 1] * W_w[(size_t)(k + 1) * UNITS + v];
        a2 += srow[k + 2] * W_w[(size_t)(k + 2) * UNITS + v];
        a3 += srow[k + 3] * W_w[(size_t)(k + 3) * UNITS + v];
    }
    g_wsb[b * UNITS + v] = (a0 + a1) + (a2 + a3) + W_b[v] + U_b[v];
}

// ---------------------------------------------------------------------------
// Kernel 2: fused GEMM + tanh·V epilogue.
// C = A(hidden)[M_TOTAL x 1024] @ U_w[1024 x 1024]; per N-tile of 128,
// emit partial score = sum_n V[n] * tanh(wsb[b,n] + C[m,n]).
// BM=128, BN=128, BK=8, 256 threads, 8x8 per thread.
// grid = (M_TOTAL/128, 8)
// ---------------------------------------------------------------------------
__global__ __launch_bounds__(256, 2)
void score_gemm_kernel(const float* __restrict__ A,
                       const float* __restrict__ Bmat,   // U_w
                       const float* __restrict__ V) {    // V_w [1024]
    __shared__ float As[8][128];
    __shared__ float Bs[8][128];

    const int bm  = blockIdx.x;            // 0..1023
    const int bn  = blockIdx.y;            // 0..7
    const int tid = threadIdx.x;
    const int tx  = tid & 15;              // 0..15 (N direction)
    const int ty  = tid >> 4;              // 0..15 (M direction)

    const float* Ablk = A + (size_t)bm * 128 * UNITS;
    const float* Bblk = Bmat + bn * 128;

    float acc[8][8];
    #pragma unroll
    for (int i = 0; i < 8; i++)
        #pragma unroll
        for (int j = 0; j < 8; j++)
            acc[i][j] = 0.f;

    // load index precompute
    const int arow  = tid >> 1;            // 0..127
    const int acol4 = (tid & 1) * 4;       // 0 or 4
    const int brow  = tid >> 5;            // 0..7
    const int bcol4 = (tid & 31) * 4;      // 0..124

    for (int k0 = 0; k0 < UNITS; k0 += 8) {
        float4 av = *(const float4*)(Ablk + (size_t)arow * UNITS + k0 + acol4);
        As[acol4 + 0][arow] = av.x;
        As[acol4 + 1][arow] = av.y;
        As[acol4 + 2][arow] = av.z;
        As[acol4 + 3][arow] = av.w;
        float4 bv = *(const float4*)(Bblk + (size_t)(k0 + brow) * UNITS + bcol4);
        *(float4*)&Bs[brow][bcol4] = bv;
        __syncthreads();

        #pragma unroll
        for (int kk = 0; kk < 8; kk++) {
            float af[8], bf[8];
            #pragma unroll
            for (int i = 0; i < 8; i++) af[i] = As[kk][ty * 8 + i];
            #pragma unroll
            for (int j = 0; j < 8; j++) bf[j] = Bs[kk][tx * 8 + j];
            #pragma unroll
            for (int i = 0; i < 8; i++)
                #pragma unroll
                for (int j = 0; j < 8; j++)
                    acc[i][j] += af[i] * bf[j];
        }
        __syncthreads();
    }

    // Epilogue: partial score = sum_n V[n] * tanh(wsb[b,n] + acc)
    __shared__ float Vs[128];
    __shared__ float Ws[128];
    const int b = (bm * 128) / SEQ;        // whole 128-row tile is one batch (4096 % 128 == 0)
    if (tid < 128) {
        Vs[tid] = V[bn * 128 + tid];
        Ws[tid] = g_wsb[b * UNITS + bn * 128 + tid];
    }
    __syncthreads();

    float rowsum[8];
    #pragma unroll
    for (int i = 0; i < 8; i++) {
        float s = 0.f;
        #pragma unroll
        for (int j = 0; j < 8; j++) {
            int n = tx * 8 + j;
            s += Vs[n] * tanhf(Ws[n] + acc[i][j]);
        }
        // reduce over the 16 tx lanes (aligned 16-lane groups within the warp)
        s += __shfl_xor_sync(0xffffffffu, s, 1);
        s += __shfl_xor_sync(0xffffffffu, s, 2);
        s += __shfl_xor_sync(0xffffffffu, s, 4);
        s += __shfl_xor_sync(0xffffffffu, s, 8);
        rowsum[i] = s;
    }
    if (tx == 0) {
        int mbase = bm * 128 + ty * 8;
        #pragma unroll
        for (int i = 0; i < 8; i++)
            g_score_part[(size_t)(mbase + i) * NBLK + bn] = rowsum[i];
    }
}

// ---------------------------------------------------------------------------
// Kernel 3: softmax over S per batch. grid = BATCH, block = 1024.
// Sums the NBLK partials + V_b, softmax, writes weights to d_out region.
// ---------------------------------------------------------------------------
__global__ void softmax_kernel(float* __restrict__ weights_out,
                               const float* __restrict__ V_b) {
    __shared__ float red[1024];
    const int b = blockIdx.x;
    const int t = threadIdx.x;
    const float vb = V_b[0];

    float sc[4];
    float mx = -1e30f;
    #pragma unroll
    for (int j = 0; j < 4; j++) {
        int s = t + j * 1024;
        const float* p = &g_score_part[(size_t)(b * SEQ + s) * NBLK];
        float v = vb;
        #pragma unroll
        for (int q = 0; q < NBLK; q++) v += p[q];
        sc[j] = v;
        mx = fmaxf(mx, v);
    }
    red[t] = mx;
    __syncthreads();
    for (int o = 512; o > 0; o >>= 1) {
        if (t < o) red[t] = fmaxf(red[t], red[t + o]);
        __syncthreads();
    }
    mx = red[0];
    __syncthreads();

    float e[4];
    float sum = 0.f;
    #pragma unroll
    for (int j = 0; j < 4; j++) {
        e[j] = expf(sc[j] - mx);
        sum += e[j];
    }
    red[t] = sum;
    __syncthreads();
    for (int o = 512; o > 0; o >>= 1) {
        if (t < o) red[t] += red[t + o];
        __syncthreads();
    }
    float inv = 1.f / red[0];
    #pragma unroll
    for (int j = 0; j < 4; j++)
        weights_out[b * SEQ + t + j * 1024] = e[j] * inv;
}

// ---------------------------------------------------------------------------
// Kernel 4: partial context over S-splits. grid = (BATCH, 8), block = 1024.
// ---------------------------------------------------------------------------
__global__ void ctx_partial_kernel(const float* __restrict__ H,
                                   const float* __restrict__ W) {
    const int b = blockIdx.x;
    const int c = blockIdx.y;      // s-chunk of 512
    const int u = threadIdx.x;
    const float* w = W + b * SEQ + c * 512;
    const float* h = H + ((size_t)b * SEQ + c * 512) * UNITS + u;
    float a0 = 0.f, a1 = 0.f, a2 = 0.f, a3 = 0.f;
    for (int s = 0; s < 512; s += 4) {
        a0 += w[s + 0] * h[(size_t)(s + 0) * UNITS];
        a1 += w[s + 1] * h[(size_t)(s + 1) * UNITS];
        a2 += w[s + 2] * h[(size_t)(s + 2) * UNITS];
        a3 += w[s + 3] * h[(size_t)(s + 3) * UNITS];
    }
    g_ctx_part[(b * 8 + c) * UNITS + u] = (a0 + a1) + (a2 + a3);
}

// ---------------------------------------------------------------------------
// Kernel 5: combine the 8 S-split partials. grid = BATCH, block = 1024.
// ---------------------------------------------------------------------------
__global__ void ctx_reduce_kernel(float* __restrict__ ctx_out) {
    const int b = blockIdx.x;
    const int u = threadIdx.x;
    float acc = 0.f;
    #pragma unroll
    for (int c = 0; c < 8; c++)
        acc += g_ctx_part[(b * 8 + c) * UNITS + u];
    ctx_out[b * UNITS + u] = acc;
}

// ---------------------------------------------------------------------------
extern "C" void kernel_launch(void* const* d_in, const int* in_sizes, int n_in,
                              void* d_out, int out_size) {
    const float* s_prev = (const float*)d_in[0];   // [32,1024]
    const float* hidden = (const float*)d_in[1];   // [32,4096,1024]
    const float* W_w    = (const float*)d_in[2];   // [1024,1024]
    const float* W_b    = (const float*)d_in[3];   // [1024]
    const float* U_w    = (const float*)d_in[4];   // [1024,1024]
    const float* U_b    = (const float*)d_in[5];   // [1024]
    const float* V_w    = (const float*)d_in[6];   // [1024,1]
    const float* V_b    = (const float*)d_in[7];   // [1]

    float* out     = (float*)d_out;
    float* ctx_out = out;                      // [32,1024]
    float* w_out   = out + BATCH * UNITS;      // [32,4096,1]

    ws_kernel<<<BATCH, UNITS>>>(s_prev, W_w, W_b, U_b);
    dim3 g(M_TOTAL / 128, NBLK);
    score_gemm_kernel<<<g, 256>>>(hidden, U_w, V_w);
    softmax_kernel<<<BATCH, 1024>>>(w_out, V_b);
    ctx_partial_kernel<<<dim3(BATCH, 8), 1024>>>(hidden, w_out);
    ctx_reduce_kernel<<<BATCH, 1024>>>(ctx_out);
}

// round 3
// speedup vs baseline: 1.8870x; 1.8870x over previous
#include <cuda_runtime.h>
#include <cuda_bf16.h>
#include <cstdint>
#include <math.h>

#define BATCH 32
#define SEQ   4096
#define UNITS 1024
#define M_TOTAL (BATCH * SEQ)      // 131072
#define NBLK  8                    // 8 n-tiles of 128
#define KC    32                   // k chunk
#define NCHUNK (UNITS / KC)        // 32
#define KPAD  40                   // smem row pitch in elements (conflict-free)

// ---------------------------------------------------------------------------
// Scratch (device globals)
// ---------------------------------------------------------------------------
__device__ __nv_bfloat16 g_Bhi[(size_t)UNITS * UNITS];     // U_w^T [n][k] hi
__device__ __nv_bfloat16 g_Blo[(size_t)UNITS * UNITS];     // U_w^T [n][k] lo
__device__ float g_wsb[BATCH * UNITS];
__device__ float g_score_part[(size_t)M_TOTAL * NBLK];
__device__ float g_ctx_part[BATCH * 8 * UNITS];

// ---------------------------------------------------------------------------
// mma.sync m16n8k16 bf16 (standard PTX, works at compute_103)
// ---------------------------------------------------------------------------
__device__ __forceinline__ void mma_bf16(float c[4], const uint32_t a[4], const uint32_t b[2]) {
    asm volatile(
        "mma.sync.aligned.m16n8k16.row.col.f32.bf16.bf16.f32 "
        "{%0,%1,%2,%3}, {%4,%5,%6,%7}, {%8,%9}, {%0,%1,%2,%3};"
        : "+f"(c[0]), "+f"(c[1]), "+f"(c[2]), "+f"(c[3])
        : "r"(a[0]), "r"(a[1]), "r"(a[2]), "r"(a[3]), "r"(b[0]), "r"(b[1]));
}

// ---------------------------------------------------------------------------
// Prep: U_w [k][n] fp32 -> transposed bf16 hi/lo [n][k]
// ---------------------------------------------------------------------------
__global__ void convB_kernel(const float* __restrict__ U) {
    __shared__ float t[32][33];
    int n0 = blockIdx.x * 32, k0 = blockIdx.y * 32;
    t[threadIdx.y][threadIdx.x] = U[(size_t)(k0 + threadIdx.y) * UNITS + n0 + threadIdx.x];
    __syncthreads();
    float v = t[threadIdx.x][threadIdx.y];   // = U[k0+tx][n0+ty]
    __nv_bfloat16 h = __float2bfloat16(v);
    size_t o = (size_t)(n0 + threadIdx.y) * UNITS + k0 + threadIdx.x;
    g_Bhi[o] = h;
    g_Blo[o] = __float2bfloat16(v - __bfloat162float(h));
}

// ---------------------------------------------------------------------------
// Prep: wsb = s_prev@W_w + W_b + U_b
// ---------------------------------------------------------------------------
__global__ void ws_kernel(const float* __restrict__ s_prev,
                          const float* __restrict__ W_w,
                          const float* __restrict__ W_b,
                          const float* __restrict__ U_b) {
    __shared__ float srow[UNITS];
    int b = blockIdx.x, v = threadIdx.x;
    srow[v] = s_prev[b * UNITS + v];
    __syncthreads();
    float a0 = 0.f, a1 = 0.f, a2 = 0.f, a3 = 0.f;
    #pragma unroll 4
    for (int k = 0; k < UNITS; k += 4) {
        a0 += srow[k + 0] * W_w[(size_t)(k + 0) * UNITS + v];
        a1 += srow[k + 1] * W_w[(size_t)(k + 1) * UNITS + v];
        a2 += srow[k + 2] * W_w[(size_t)(k + 2) * UNITS + v];
        a3 += srow[k + 3] * W_w[(size_t)(k + 3) * UNITS + v];
    }
    g_wsb[b * UNITS + v] = (a0 + a1) + (a2 + a3) + W_b[v] + U_b[v];
}

// ---------------------------------------------------------------------------
// Main: mma.sync bf16 3-term GEMM + tanh·V epilogue.
// grid = (NBLK, M_TOTAL/128); block = 256 (8 warps as 4(m) x 2(n)).
// Warp tile 32(m) x 64(n). A split to bf16 hi/lo on the fly.
// ---------------------------------------------------------------------------
__global__ __launch_bounds__(256, 1)
void score_gemm_mma(const float* __restrict__ A,     // hidden fp32
                    const float* __restrict__ V) {   // V_w [1024]
    __shared__ __nv_bfloat16 Ah_s[128 * KPAD];
    __shared__ __nv_bfloat16 Al_s[128 * KPAD];
    __shared__ __nv_bfloat16 Bh_s[128 * KPAD];
    __shared__ __nv_bfloat16 Bl_s[128 * KPAD];
    __shared__ float sc_s[128][2];
    __shared__ float Ws[128];
    __shared__ float Vs[128];

    const int nt     = blockIdx.x;          // 0..7
    const int mtile  = blockIdx.y;          // 0..1023
    const int tid    = threadIdx.x;
    const int lane   = tid & 31;
    const int wid    = tid >> 5;
    const int wm     = wid & 3;             // 0..3  (m)
    const int wn     = wid >> 2;            // 0..1  (n)
    const int g      = lane >> 2;           // 0..7
    const int tc     = (lane & 3) * 2;      // 0,2,4,6
    const int b      = mtile >> 5;          // batch

    if (tid < 128) {
        Ws[tid] = g_wsb[b * UNITS + nt * 128 + tid];
        Vs[tid] = V[nt * 128 + tid];
    }

    float c[2][8][4];
    #pragma unroll
    for (int mi = 0; mi < 2; mi++)
        #pragma unroll
        for (int nf = 0; nf < 8; nf++)
            #pragma unroll
            for (int q = 0; q < 4; q++)
                c[mi][nf][q] = 0.f;

    // per-thread load geometry
    const int row = tid >> 1;               // 0..127
    const int hf  = tid & 1;                // 0/1 (16-element half)
    const float* aptr0 = A + (size_t)(mtile * 128 + row) * UNITS + hf * 16;
    const __nv_bfloat16* bh0 = g_Bhi + (size_t)(nt * 128 + row) * UNITS + hf * 16;
    const __nv_bfloat16* bl0 = g_Blo + (size_t)(nt * 128 + row) * UNITS + hf * 16;

    float4 ra[4];
    uint4  rbh[2], rbl[2];

    // prefetch chunk 0
    {
        const float* p = aptr0;
        #pragma unroll
        for (int q = 0; q < 4; q++) ra[q] = *(const float4*)(p + q * 4);
        #pragma unroll
        for (int q = 0; q < 2; q++) {
            rbh[q] = *(const uint4*)(bh0 + q * 8);
            rbl[q] = *(const uint4*)(bl0 + q * 8);
        }
    }

    for (int kc = 0; kc < NCHUNK; kc++) {
        // store staged regs -> smem
        {
            __nv_bfloat16* ah = Ah_s + row * KPAD + hf * 16;
            __nv_bfloat16* al = Al_s + row * KPAD + hf * 16;
            #pragma unroll
            for (int q = 0; q < 4; q++) {
                float4 v = ra[q];
                __nv_bfloat162 h01 = __floats2bfloat162_rn(v.x, v.y);
                __nv_bfloat162 h23 = __floats2bfloat162_rn(v.z, v.w);
                __nv_bfloat162 l01 = __floats2bfloat162_rn(
                    v.x - __bfloat162float(h01.x), v.y - __bfloat162float(h01.y));
                __nv_bfloat162 l23 = __floats2bfloat162_rn(
                    v.z - __bfloat162float(h23.x), v.w - __bfloat162float(h23.y));
                *(__nv_bfloat162*)(ah + q * 4)     = h01;
                *(__nv_bfloat162*)(ah + q * 4 + 2) = h23;
                *(__nv_bfloat162*)(al + q * 4)     = l01;
                *(__nv_bfloat162*)(al + q * 4 + 2) = l23;
            }
            *(uint4*)(Bh_s + row * KPAD + hf * 16)     = rbh[0];
            *(uint4*)(Bh_s + row * KPAD + hf * 16 + 8) = rbh[1];
            *(uint4*)(Bl_s + row * KPAD + hf * 16)     = rbl[0];
            *(uint4*)(Bl_s + row * KPAD + hf * 16 + 8) = rbl[1];
        }
        __syncthreads();

        // prefetch next chunk (global -> regs) while computing
        if (kc + 1 < NCHUNK) {
            const float* p = aptr0 + (kc + 1) * KC;
            #pragma unroll
            for (int q = 0; q < 4; q++) ra[q] = *(const float4*)(p + q * 4);
            #pragma unroll
            for (int q = 0; q < 2; q++) {
                rbh[q] = *(const uint4*)(bh0 + (kc + 1) * KC + q * 8);
                rbl[q] = *(const uint4*)(bl0 + (kc + 1) * KC + q * 8);
            }
        }

        // compute: two k16 steps
        #pragma unroll
        for (int ks = 0; ks < 2; ks++) {
            const int kb = ks * 16;
            uint32_t ah[2][4], al[2][4];
            #pragma unroll
            for (int mi = 0; mi < 2; mi++) {
                int r0 = wm * 32 + mi * 16 + g;
                const __nv_bfloat16* ph = Ah_s + r0 * KPAD + kb + tc;
                const __nv_bfloat16* pl = Al_s + r0 * KPAD + kb + tc;
                ah[mi][0] = *(const uint32_t*)(ph);
                ah[mi][1] = *(const uint32_t*)(ph + 8 * KPAD);
                ah[mi][2] = *(const uint32_t*)(ph + 8);
                ah[mi][3] = *(const uint32_t*)(ph + 8 * KPAD + 8);
                al[mi][0] = *(const uint32_t*)(pl);
                al[mi][1] = *(const uint32_t*)(pl + 8 * KPAD);
                al[mi][2] = *(const uint32_t*)(pl + 8);
                al[mi][3] = *(const uint32_t*)(pl + 8 * KPAD + 8);
            }
            uint32_t bh[8][2], bl[8][2];
            #pragma unroll
            for (int nf = 0; nf < 8; nf++) {
                int n0 = wn * 64 + nf * 8 + g;
                const __nv_bfloat16* ph = Bh_s + n0 * KPAD + kb + tc;
                const __nv_bfloat16* pl = Bl_s + n0 * KPAD + kb + tc;
                bh[nf][0] = *(const uint32_t*)(ph);
                bh[nf][1] = *(const uint32_t*)(ph + 8);
                bl[nf][0] = *(const uint32_t*)(pl);
                bl[nf][1] = *(const uint32_t*)(pl + 8);
            }
            #pragma unroll
            for (int mi = 0; mi < 2; mi++)
                #pragma unroll
                for (int nf = 0; nf < 8; nf++) {
                    mma_bf16(c[mi][nf], ah[mi], bh[nf]);   // hi*hi
                    mma_bf16(c[mi][nf], ah[mi], bl[nf]);   // hi*lo
                    mma_bf16(c[mi][nf], al[mi], bh[nf]);   // lo*hi
                }
        }
        __syncthreads();
    }

    // ---- epilogue: partial score = sum_n V[n] * tanh(Ws[n] + C[m,n]) ----
    #pragma unroll
    for (int mi = 0; mi < 2; mi++) {
        float sa = 0.f, sb = 0.f;
        #pragma unroll
        for (int nf = 0; nf < 8; nf++) {
            int n0 = wn * 64 + nf * 8 + tc;
            sa += Vs[n0]     * tanhf(Ws[n0]     + c[mi][nf][0]);
            sa += Vs[n0 + 1] * tanhf(Ws[n0 + 1] + c[mi][nf][1]);
            sb += Vs[n0]     * tanhf(Ws[n0]     + c[mi][nf][2]);
            sb += Vs[n0 + 1] * tanhf(Ws[n0 + 1] + c[mi][nf][3]);
        }
        sa += __shfl_xor_sync(0xffffffffu, sa, 1);
        sa += __shfl_xor_sync(0xffffffffu, sa, 2);
        sb += __shfl_xor_sync(0xffffffffu, sb, 1);
        sb += __shfl_xor_sync(0xffffffffu, sb, 2);
        if ((lane & 3) == 0) {
            int r0 = wm * 32 + mi * 16 + g;
            sc_s[r0][wn]     = sa;
            sc_s[r0 + 8][wn] = sb;
        }
    }
    __syncthreads();
    if (tid < 128) {
        g_score_part[((size_t)mtile * 128 + tid) * NBLK + nt] =
            sc_s[tid][0] + sc_s[tid][1];
    }
}

// ---------------------------------------------------------------------------
// Softmax over S per batch (sums NBLK partials + V_b), writes weights.
// ---------------------------------------------------------------------------
__global__ void softmax_kernel(float* __restrict__ weights_out,
                               const float* __restrict__ V_b) {
    __shared__ float red[1024];
    const int b = blockIdx.x, t = threadIdx.x;
    const float vb = V_b[0];

    float sc[4];
    float mx = -1e30f;
    #pragma unroll
    for (int j = 0; j < 4; j++) {
        int s = t + j * 1024;
        const float* p = &g_score_part[(size_t)(b * SEQ + s) * NBLK];
        float v = vb;
        #pragma unroll
        for (int q = 0; q < NBLK; q++) v += p[q];
        sc[j] = v;
        mx = fmaxf(mx, v);
    }
    red[t] = mx;
    __syncthreads();
    for (int o = 512; o > 0; o >>= 1) {
        if (t < o) red[t] = fmaxf(red[t], red[t + o]);
        __syncthreads();
    }
    mx = red[0];
    __syncthreads();

    float e[4], sum = 0.f;
    #pragma unroll
    for (int j = 0; j < 4; j++) { e[j] = expf(sc[j] - mx); sum += e[j]; }
    red[t] = sum;
    __syncthreads();
    for (int o = 512; o > 0; o >>= 1) {
        if (t < o) red[t] += red[t + o];
        __syncthreads();
    }
    float inv = 1.f / red[0];
    #pragma unroll
    for (int j = 0; j < 4; j++)
        weights_out[b * SEQ + t + j * 1024] = e[j] * inv;
}

// ---------------------------------------------------------------------------
// Context: weighted sum of hidden over S.
// ---------------------------------------------------------------------------
__global__ void ctx_partial_kernel(const float* __restrict__ H,
                                   const float* __restrict__ W) {
    const int b = blockIdx.x, cs = blockIdx.y, u = threadIdx.x;
    const float* w = W + b * SEQ + cs * 512;
    const float* h = H + ((size_t)b * SEQ + cs * 512) * UNITS + u;
    float a0 = 0.f, a1 = 0.f, a2 = 0.f, a3 = 0.f;
    for (int s = 0; s < 512; s += 4) {
        a0 += w[s + 0] * h[(size_t)(s + 0) * UNITS];
        a1 += w[s + 1] * h[(size_t)(s + 1) * UNITS];
        a2 += w[s + 2] * h[(size_t)(s + 2) * UNITS];
        a3 += w[s + 3] * h[(size_t)(s + 3) * UNITS];
    }
    g_ctx_part[(b * 8 + cs) * UNITS + u] = (a0 + a1) + (a2 + a3);
}

__global__ void ctx_reduce_kernel(float* __restrict__ ctx_out) {
    const int b = blockIdx.x, u = threadIdx.x;
    float acc = 0.f;
    #pragma unroll
    for (int cs = 0; cs < 8; cs++)
        acc += g_ctx_part[(b * 8 + cs) * UNITS + u];
    ctx_out[b * UNITS + u] = acc;
}

// ---------------------------------------------------------------------------
extern "C" void kernel_launch(void* const* d_in, const int* in_sizes, int n_in,
                              void* d_out, int out_size) {
    const float* s_prev = (const float*)d_in[0];
    const float* hidden = (const float*)d_in[1];
    const float* W_w    = (const float*)d_in[2];
    const float* W_b    = (const float*)d_in[3];
    const float* U_w    = (const float*)d_in[4];
    const float* U_b    = (const float*)d_in[5];
    const float* V_w    = (const float*)d_in[6];
    const float* V_b    = (const float*)d_in[7];

    float* out     = (float*)d_out;
    float* ctx_out = out;                      // [32,1024]
    float* w_out   = out + BATCH * UNITS;      // [32,4096,1]

    convB_kernel<<<dim3(32, 32), dim3(32, 32)>>>(U_w);
    ws_kernel<<<BATCH, UNITS>>>(s_prev, W_w, W_b, U_b);
    score_gemm_mma<<<dim3(NBLK, M_TOTAL / 128), 256>>>(hidden, V_w);
    softmax_kernel<<<BATCH, 1024>>>(w_out, V_b);
    ctx_partial_kernel<<<dim3(BATCH, 8), 1024>>>(hidden, w_out);
    ctx_reduce_kernel<<<BATCH, 1024>>>(ctx_out);
}

// round 4
// speedup vs baseline: 2.6945x; 1.4279x over previous
#include <cuda_runtime.h>
#include <cuda_fp16.h>
#include <cstdint>
#include <math.h>

#define BATCH 32
#define SEQ   4096
#define UNITS 1024
#define M_TOTAL (BATCH * SEQ)      // 131072
#define NBLK  8                    // 8 n-tiles of 128
#define KC    32                   // k chunk
#define NCHUNK (UNITS / KC)        // 32
#define KPAD  40                   // smem row pitch in elements (conflict-free)

// ---------------------------------------------------------------------------
// Scratch (device globals)
// ---------------------------------------------------------------------------
__device__ __half g_Bh[(size_t)UNITS * UNITS];    // U_w^T [n][k] fp16
__device__ float g_wsb[BATCH * UNITS];
__device__ float g_score_part[(size_t)M_TOTAL * NBLK];
__device__ float g_ctx_part[BATCH * 8 * UNITS];

// ---------------------------------------------------------------------------
// mma.sync m16n8k16 fp16 inputs, fp32 accum (standard PTX, ok at compute_103)
// ---------------------------------------------------------------------------
__device__ __forceinline__ void mma_f16(float c[4], const uint32_t a[4], const uint32_t b[2]) {
    asm volatile(
        "mma.sync.aligned.m16n8k16.row.col.f32.f16.f16.f32 "
        "{%0,%1,%2,%3}, {%4,%5,%6,%7}, {%8,%9}, {%0,%1,%2,%3};"
        : "+f"(c[0]), "+f"(c[1]), "+f"(c[2]), "+f"(c[3])
        : "r"(a[0]), "r"(a[1]), "r"(a[2]), "r"(a[3]), "r"(b[0]), "r"(b[1]));
}

// ---------------------------------------------------------------------------
// Prep: U_w [k][n] fp32 -> transposed fp16 [n][k]
// ---------------------------------------------------------------------------
__global__ void convB_kernel(const float* __restrict__ U) {
    __shared__ float t[32][33];
    int n0 = blockIdx.x * 32, k0 = blockIdx.y * 32;
    t[threadIdx.y][threadIdx.x] = U[(size_t)(k0 + threadIdx.y) * UNITS + n0 + threadIdx.x];
    __syncthreads();
    float v = t[threadIdx.x][threadIdx.y];   // = U[k0+tx][n0+ty]
    g_Bh[(size_t)(n0 + threadIdx.y) * UNITS + k0 + threadIdx.x] = __float2half_rn(v);
}

// ---------------------------------------------------------------------------
// Prep: wsb = s_prev@W_w + W_b + U_b
// ---------------------------------------------------------------------------
__global__ void ws_kernel(const float* __restrict__ s_prev,
                          const float* __restrict__ W_w,
                          const float* __restrict__ W_b,
                          const float* __restrict__ U_b) {
    __shared__ float srow[UNITS];
    int b = blockIdx.x, v = threadIdx.x;
    srow[v] = s_prev[b * UNITS + v];
    __syncthreads();
    float a0 = 0.f, a1 = 0.f, a2 = 0.f, a3 = 0.f;
    #pragma unroll 4
    for (int k = 0; k < UNITS; k += 4) {
        a0 += srow[k + 0] * W_w[(size_t)(k + 0) * UNITS + v];
        a1 += srow[k + 1] * W_w[(size_t)(k + 1) * UNITS + v];
        a2 += srow[k + 2] * W_w[(size_t)(k + 2) * UNITS + v];
        a3 += srow[k + 3] * W_w[(size_t)(k + 3) * UNITS + v];
    }
    g_wsb[b * UNITS + v] = (a0 + a1) + (a2 + a3) + W_b[v] + U_b[v];
}

// ---------------------------------------------------------------------------
// Main: mma.sync fp16 2-term GEMM + tanh·V epilogue.
// grid = (NBLK, M_TOTAL/128); block = 256 (8 warps as 4(m) x 2(n)).
// Warp tile 32(m) x 64(n). A split to fp16 hi/lo on the fly; B single fp16.
// C = (Ah + Al) @ Bh  (dropped term: A*(B - Bh) ~ 1e-4 relative)
// ---------------------------------------------------------------------------
__global__ __launch_bounds__(256, 1)
void score_gemm_mma(const float* __restrict__ A,     // hidden fp32
                    const float* __restrict__ V) {   // V_w [1024]
    __shared__ __half Ah_s[128 * KPAD];
    __shared__ __half Al_s[128 * KPAD];
    __shared__ __half Bh_s[128 * KPAD];
    __shared__ float sc_s[128][2];
    __shared__ float Ws[128];
    __shared__ float Vs[128];

    const int nt     = blockIdx.x;          // 0..7
    const int mtile  = blockIdx.y;          // 0..1023
    const int tid    = threadIdx.x;
    const int lane   = tid & 31;
    const int wid    = tid >> 5;
    const int wm     = wid & 3;             // 0..3  (m)
    const int wn     = wid >> 2;            // 0..1  (n)
    const int g      = lane >> 2;           // 0..7
    const int tc     = (lane & 3) * 2;      // 0,2,4,6
    const int b      = mtile >> 5;          // batch

    if (tid < 128) {
        Ws[tid] = g_wsb[b * UNITS + nt * 128 + tid];
        Vs[tid] = V[nt * 128 + tid];
    }

    float c[2][8][4];
    #pragma unroll
    for (int mi = 0; mi < 2; mi++)
        #pragma unroll
        for (int nf = 0; nf < 8; nf++)
            #pragma unroll
            for (int q = 0; q < 4; q++)
                c[mi][nf][q] = 0.f;

    // per-thread load geometry
    const int row = tid >> 1;               // 0..127
    const int hf  = tid & 1;                // 0/1 (16-element half)
    const float* aptr0 = A + (size_t)(mtile * 128 + row) * UNITS + hf * 16;
    const __half* bh0  = g_Bh + (size_t)(nt * 128 + row) * UNITS + hf * 16;

    float4 ra[4];
    uint4  rbh[2];

    // prefetch chunk 0
    {
        #pragma unroll
        for (int q = 0; q < 4; q++) ra[q] = *(const float4*)(aptr0 + q * 4);
        #pragma unroll
        for (int q = 0; q < 2; q++) rbh[q] = *(const uint4*)(bh0 + q * 8);
    }

    for (int kc = 0; kc < NCHUNK; kc++) {
        // store staged regs -> smem (split A into fp16 hi + lo)
        {
            __half* ah = Ah_s + row * KPAD + hf * 16;
            __half* al = Al_s + row * KPAD + hf * 16;
            #pragma unroll
            for (int q = 0; q < 4; q++) {
                float4 v = ra[q];
                __half h0 = __float2half_rn(v.x), h1 = __float2half_rn(v.y);
                __half h2 = __float2half_rn(v.z), h3 = __float2half_rn(v.w);
                __half l0 = __float2half_rn(v.x - __half2float(h0));
                __half l1 = __float2half_rn(v.y - __half2float(h1));
                __half l2 = __float2half_rn(v.z - __half2float(h2));
                __half l3 = __float2half_rn(v.w - __half2float(h3));
                *(__half2*)(ah + q * 4)     = __half2{h0, h1};
                *(__half2*)(ah + q * 4 + 2) = __half2{h2, h3};
                *(__half2*)(al + q * 4)     = __half2{l0, l1};
                *(__half2*)(al + q * 4 + 2) = __half2{l2, l3};
            }
            *(uint4*)(Bh_s + row * KPAD + hf * 16)     = rbh[0];
            *(uint4*)(Bh_s + row * KPAD + hf * 16 + 8) = rbh[1];
        }
        __syncthreads();

        // prefetch next chunk (global -> regs) while computing
        if (kc + 1 < NCHUNK) {
            const float* p = aptr0 + (kc + 1) * KC;
            #pragma unroll
            for (int q = 0; q < 4; q++) ra[q] = *(const float4*)(p + q * 4);
            #pragma unroll
            for (int q = 0; q < 2; q++)
                rbh[q] = *(const uint4*)(bh0 + (kc + 1) * KC + q * 8);
        }

        // compute: two k16 steps
        #pragma unroll
        for (int ks = 0; ks < 2; ks++) {
            const int kb = ks * 16;
            uint32_t ah[2][4], al[2][4];
            #pragma unroll
            for (int mi = 0; mi < 2; mi++) {
                int r0 = wm * 32 + mi * 16 + g;
                const __half* ph = Ah_s + r0 * KPAD + kb + tc;
                const __half* pl = Al_s + r0 * KPAD + kb + tc;
                ah[mi][0] = *(const uint32_t*)(ph);
                ah[mi][1] = *(const uint32_t*)(ph + 8 * KPAD);
                ah[mi][2] = *(const uint32_t*)(ph + 8);
                ah[mi][3] = *(const uint32_t*)(ph + 8 * KPAD + 8);
                al[mi][0] = *(const uint32_t*)(pl);
                al[mi][1] = *(const uint32_t*)(pl + 8 * KPAD);
                al[mi][2] = *(const uint32_t*)(pl + 8);
                al[mi][3] = *(const uint32_t*)(pl + 8 * KPAD + 8);
            }
            uint32_t bh[8][2];
            #pragma unroll
            for (int nf = 0; nf < 8; nf++) {
                int n0 = wn * 64 + nf * 8 + g;
                const __half* ph = Bh_s + n0 * KPAD + kb + tc;
                bh[nf][0] = *(const uint32_t*)(ph);
                bh[nf][1] = *(const uint32_t*)(ph + 8);
            }
            #pragma unroll
            for (int mi = 0; mi < 2; mi++)
                #pragma unroll
                for (int nf = 0; nf < 8; nf++) {
                    mma_f16(c[mi][nf], ah[mi], bh[nf]);   // hi*B
                    mma_f16(c[mi][nf], al[mi], bh[nf]);   // lo*B
                }
        }
        __syncthreads();
    }

    // ---- epilogue: partial score = sum_n V[n] * tanh(Ws[n] + C[m,n]) ----
    #pragma unroll
    for (int mi = 0; mi < 2; mi++) {
        float sa = 0.f, sb = 0.f;
        #pragma unroll
        for (int nf = 0; nf < 8; nf++) {
            int n0 = wn * 64 + nf * 8 + tc;
            sa += Vs[n0]     * tanhf(Ws[n0]     + c[mi][nf][0]);
            sa += Vs[n0 + 1] * tanhf(Ws[n0 + 1] + c[mi][nf][1]);
            sb += Vs[n0]     * tanhf(Ws[n0]     + c[mi][nf][2]);
            sb += Vs[n0 + 1] * tanhf(Ws[n0 + 1] + c[mi][nf][3]);
        }
        sa += __shfl_xor_sync(0xffffffffu, sa, 1);
        sa += __shfl_xor_sync(0xffffffffu, sa, 2);
        sb += __shfl_xor_sync(0xffffffffu, sb, 1);
        sb += __shfl_xor_sync(0xffffffffu, sb, 2);
        if ((lane & 3) == 0) {
            int r0 = wm * 32 + mi * 16 + g;
            sc_s[r0][wn]     = sa;
            sc_s[r0 + 8][wn] = sb;
        }
    }
    __syncthreads();
    if (tid < 128) {
        g_score_part[((size_t)mtile * 128 + tid) * NBLK + nt] =
            sc_s[tid][0] + sc_s[tid][1];
    }
}

// ---------------------------------------------------------------------------
// Softmax over S per batch (sums NBLK partials + V_b), writes weights.
// ---------------------------------------------------------------------------
__global__ void softmax_kernel(float* __restrict__ weights_out,
                               const float* __restrict__ V_b) {
    __shared__ float red[1024];
    const int b = blockIdx.x, t = threadIdx.x;
    const float vb = V_b[0];

    float sc[4];
    float mx = -1e30f;
    #pragma unroll
    for (int j = 0; j < 4; j++) {
        int s = t + j * 1024;
        const float* p = &g_score_part[(size_t)(b * SEQ + s) * NBLK];
        float v = vb;
        #pragma unroll
        for (int q = 0; q < NBLK; q++) v += p[q];
        sc[j] = v;
        mx = fmaxf(mx, v);
    }
    red[t] = mx;
    __syncthreads();
    for (int o = 512; o > 0; o >>= 1) {
        if (t < o) red[t] = fmaxf(red[t], red[t + o]);
        __syncthreads();
    }
    mx = red[0];
    __syncthreads();

    float e[4], sum = 0.f;
    #pragma unroll
    for (int j = 0; j < 4; j++) { e[j] = expf(sc[j] - mx); sum += e[j]; }
    red[t] = sum;
    __syncthreads();
    for (int o = 512; o > 0; o >>= 1) {
        if (t < o) red[t] += red[t + o];
        __syncthreads();
    }
    float inv = 1.f / red[0];
    #pragma unroll
    for (int j = 0; j < 4; j++)
        weights_out[b * SEQ + t + j * 1024] = e[j] * inv;
}

// ---------------------------------------------------------------------------
// Context: weighted sum of hidden over S.
// ---------------------------------------------------------------------------
__global__ void ctx_partial_kernel(const float* __restrict__ H,
                                   const float* __restrict__ W) {
    const int b = blockIdx.x, cs = blockIdx.y, u = threadIdx.x;
    const float* w = W + b * SEQ + cs * 512;
    const float* h = H + ((size_t)b * SEQ + cs * 512) * UNITS + u;
    float a0 = 0.f, a1 = 0.f, a2 = 0.f, a3 = 0.f;
    for (int s = 0; s < 512; s += 4) {
        a0 += w[s + 0] * h[(size_t)(s + 0) * UNITS];
        a1 += w[s + 1] * h[(size_t)(s + 1) * UNITS];
        a2 += w[s + 2] * h[(size_t)(s + 2) * UNITS];
        a3 += w[s + 3] * h[(size_t)(s + 3) * UNITS];
    }
    g_ctx_part[(b * 8 + cs) * UNITS + u] = (a0 + a1) + (a2 + a3);
}

__global__ void ctx_reduce_kernel(float* __restrict__ ctx_out) {
    const int b = blockIdx.x, u = threadIdx.x;
    float acc = 0.f;
    #pragma unroll
    for (int cs = 0; cs < 8; cs++)
        acc += g_ctx_part[(b * 8 + cs) * UNITS + u];
    ctx_out[b * UNITS + u] = acc;
}

// ---------------------------------------------------------------------------
extern "C" void kernel_launch(void* const* d_in, const int* in_sizes, int n_in,
                              void* d_out, int out_size) {
    const float* s_prev = (const float*)d_in[0];
    const float* hidden = (const float*)d_in[1];
    const float* W_w    = (const float*)d_in[2];
    const float* W_b    = (const float*)d_in[3];
    const float* U_w    = (const float*)d_in[4];
    const float* U_b    = (const float*)d_in[5];
    const float* V_w    = (const float*)d_in[6];
    const float* V_b    = (const float*)d_in[7];

    float* out     = (float*)d_out;
    float* ctx_out = out;                      // [32,1024]
    float* w_out   = out + BATCH * UNITS;      // [32,4096,1]

    convB_kernel<<<dim3(32, 32), dim3(32, 32)>>>(U_w);
    ws_kernel<<<BATCH, UNITS>>>(s_prev, W_w, W_b, U_b);
    score_gemm_mma<<<dim3(NBLK, M_TOTAL / 128), 256>>>(hidden, V_w);
    softmax_kernel<<<BATCH, 1024>>>(w_out, V_b);
    ctx_partial_kernel<<<dim3(BATCH, 8), 1024>>>(hidden, w_out);
    ctx_reduce_kernel<<<BATCH, 1024>>>(ctx_out);
}

// round 5
// speedup vs baseline: 3.4224x; 1.2701x over previous
#include <cuda_runtime.h>
#include <cuda_fp16.h>
#include <cstdint>
#include <math.h>

#define BATCH 32
#define SEQ   4096
#define UNITS 1024
#define M_TOTAL (BATCH * SEQ)      // 131072
#define NBLK  8
#define KC    32
#define NCHUNK 32
#define STAGES 3
#define TILE_B 8192                // 128 rows x 64 bytes (fp16, 32 k)
#define STAGE_B (3 * TILE_B)       // Ahi, Alo, Bh tiles
#define SMEM_GEMM (STAGES * STAGE_B + 1024)   // + Ws/Vs

// ---------------------------------------------------------------------------
// Scratch
// ---------------------------------------------------------------------------
__device__ __half g_Ahi[(size_t)M_TOTAL * UNITS];
__device__ __half g_Alo[(size_t)M_TOTAL * UNITS];
__device__ __half g_Bh[(size_t)UNITS * UNITS];     // U_w^T [n][k] fp16
__device__ float g_wsb[BATCH * UNITS];
__device__ float g_score_part[(size_t)M_TOTAL * NBLK];
__device__ float g_ctx_part[BATCH * 8 * UNITS];

// ---------------------------------------------------------------------------
// PTX helpers
// ---------------------------------------------------------------------------
__device__ __forceinline__ uint32_t smem_u32(const void* p) {
    uint32_t a;
    asm("{ .reg .u64 t; cvta.to.shared.u64 t, %1; cvt.u32.u64 %0, t; }" : "=r"(a) : "l"(p));
    return a;
}
__device__ __forceinline__ void cp16(uint32_t dst, const void* src) {
    asm volatile("cp.async.cg.shared.global [%0], [%1], 16;"
                 :: "r"(dst), "l"(__cvta_generic_to_global(src)) : "memory");
}
#define CP_COMMIT() asm volatile("cp.async.commit_group;" ::: "memory")
#define CP_WAIT(n)  asm volatile("cp.async.wait_group %0;" :: "n"(n) : "memory")

__device__ __forceinline__ void ldsm4(uint32_t r[4], uint32_t addr) {
    asm volatile("ldmatrix.sync.aligned.m8n8.x4.shared.b16 {%0,%1,%2,%3}, [%4];"
                 : "=r"(r[0]), "=r"(r[1]), "=r"(r[2]), "=r"(r[3]) : "r"(addr));
}
__device__ __forceinline__ void mma_f16(float c[4], const uint32_t a[4],
                                        uint32_t b0, uint32_t b1) {
    asm volatile(
        "mma.sync.aligned.m16n8k16.row.col.f32.f16.f16.f32 "
        "{%0,%1,%2,%3}, {%4,%5,%6,%7}, {%8,%9}, {%0,%1,%2,%3};"
        : "+f"(c[0]), "+f"(c[1]), "+f"(c[2]), "+f"(c[3])
        : "r"(a[0]), "r"(a[1]), "r"(a[2]), "r"(a[3]), "r"(b0), "r"(b1));
}

// swizzled smem offset (bytes) for (row, 16B-chunk c) in a 128x64B tile
__device__ __forceinline__ uint32_t swz(int row, int c) {
    return (uint32_t)(row * 64 + ((c ^ ((row >> 1) & 3)) << 4));
}

// ---------------------------------------------------------------------------
// Prep: hidden fp32 -> fp16 hi/lo
// ---------------------------------------------------------------------------
__global__ void convA_kernel(const float* __restrict__ A) {
    size_t i = ((size_t)blockIdx.x * 256 + threadIdx.x) * 8;
    float4 v0 = *(const float4*)(A + i);
    float4 v1 = *(const float4*)(A + i + 4);
    __half h[8], l[8];
    float f[8] = {v0.x, v0.y, v0.z, v0.w, v1.x, v1.y, v1.z, v1.w};
    #pragma unroll
    for (int q = 0; q < 8; q++) {
        h[q] = __float2half_rn(f[q]);
        l[q] = __float2half_rn(f[q] - __half2float(h[q]));
    }
    *(uint4*)(g_Ahi + i) = *(uint4*)h;
    *(uint4*)(g_Alo + i) = *(uint4*)l;
}

// ---------------------------------------------------------------------------
// Prep: U_w [k][n] fp32 -> transposed fp16 [n][k]
// ---------------------------------------------------------------------------
__global__ void convB_kernel(const float* __restrict__ U) {
    __shared__ float t[32][33];
    int n0 = blockIdx.x * 32, k0 = blockIdx.y * 32;
    t[threadIdx.y][threadIdx.x] = U[(size_t)(k0 + threadIdx.y) * UNITS + n0 + threadIdx.x];
    __syncthreads();
    float v = t[threadIdx.x][threadIdx.y];
    g_Bh[(size_t)(n0 + threadIdx.y) * UNITS + k0 + threadIdx.x] = __float2half_rn(v);
}

// ---------------------------------------------------------------------------
// Prep: wsb = s_prev@W_w + W_b + U_b
// ---------------------------------------------------------------------------
__global__ void ws_kernel(const float* __restrict__ s_prev,
                          const float* __restrict__ W_w,
                          const float* __restrict__ W_b,
                          const float* __restrict__ U_b) {
    __shared__ float srow[UNITS];
    int b = blockIdx.x, v = threadIdx.x;
    srow[v] = s_prev[b * UNITS + v];
    __syncthreads();
    float a0 = 0.f, a1 = 0.f, a2 = 0.f, a3 = 0.f;
    #pragma unroll 4
    for (int k = 0; k < UNITS; k += 4) {
        a0 += srow[k + 0] * W_w[(size_t)(k + 0) * UNITS + v];
        a1 += srow[k + 1] * W_w[(size_t)(k + 1) * UNITS + v];
        a2 += srow[k + 2] * W_w[(size_t)(k + 2) * UNITS + v];
        a3 += srow[k + 3] * W_w[(size_t)(k + 3) * UNITS + v];
    }
    g_wsb[b * UNITS + v] = (a0 + a1) + (a2 + a3) + W_b[v] + U_b[v];
}

// ---------------------------------------------------------------------------
// GEMM: 128x128 CTA tile, 4 warps (warp = 32m x 128n, mi=2 nf=16).
// 3-stage cp.async pipeline, ldmatrix frags, tanh·V epilogue.
// grid = (NBLK, 1024), block = 128.
// ---------------------------------------------------------------------------
__device__ __forceinline__ void issue_stage(uint32_t sbase, int slot,
                                            int mtile, int nt, int kc, int tid) {
    const uint32_t sb = sbase + slot * STAGE_B;
    const __half* srcs[3] = {
        g_Ahi + (size_t)mtile * 128 * UNITS + kc * KC,
        g_Alo + (size_t)mtile * 128 * UNITS + kc * KC,
        g_Bh  + (size_t)nt    * 128 * UNITS + kc * KC };
    #pragma unroll
    for (int t3 = 0; t3 < 3; t3++) {
        #pragma unroll
        for (int j = 0; j < 4; j++) {
            int s   = tid + j * 128;
            int row = s >> 2;
            int c   = s & 3;
            cp16(sb + t3 * TILE_B + swz(row, c),
                 srcs[t3] + (size_t)row * UNITS + c * 8);
        }
    }
}

__global__ __launch_bounds__(128)
void score_gemm_mma(const float* __restrict__ V) {
    extern __shared__ char smem[];
    float* Ws = (float*)(smem + STAGES * STAGE_B);        // [128]
    float* Vs = Ws + 128;                                  // [128]

    const int nt    = blockIdx.x;
    const int mtile = blockIdx.y;
    const int tid   = threadIdx.x;
    const int lane  = tid & 31;
    const int wm    = tid >> 5;          // warp 0..3 -> m rows wm*32..+31
    const int b     = mtile >> 5;
    const uint32_t sbase = smem_u32(smem);

    Ws[tid] = g_wsb[b * UNITS + nt * 128 + tid];
    Vs[tid] = V[nt * 128 + tid];

    float acc[2][16][4];
    #pragma unroll
    for (int mi = 0; mi < 2; mi++)
        #pragma unroll
        for (int nf = 0; nf < 16; nf++)
            #pragma unroll
            for (int q = 0; q < 4; q++)
                acc[mi][nf][q] = 0.f;

    // ldmatrix lane geometry (fixed per thread)
    const int a_row_off = ((lane >> 3) & 1) * 8 + (lane & 7);  // within m16 tile
    const int k_half    = (lane >> 4) * 8;                     // 0 or 8
    const int b_row_off = lane & 15;                           // within n16 pair

    // prologue: stages 0 and 1 in flight
    issue_stage(sbase, 0, mtile, nt, 0, tid);
    CP_COMMIT();
    issue_stage(sbase, 1, mtile, nt, 1, tid);
    CP_COMMIT();

    for (int kc = 0; kc < NCHUNK; kc++) {
        if (kc == NCHUNK - 1) { CP_WAIT(0); } else { CP_WAIT(1); }
        __syncthreads();
        if (kc + 2 < NCHUNK) {
            issue_stage(sbase, (kc + 2) % 3, mtile, nt, kc + 2, tid);
            CP_COMMIT();
        }

        const uint32_t st = sbase + (kc % 3) * STAGE_B;
        #pragma unroll
        for (int ks = 0; ks < 2; ks++) {
            const int kb = ks * 16;
            const int kcol = kb + k_half;
            const int cK = kcol >> 3;
            uint32_t ah[2][4], al[2][4];
            #pragma unroll
            for (int mi = 0; mi < 2; mi++) {
                int row = wm * 32 + mi * 16 + a_row_off;
                uint32_t off = swz(row, cK);
                ldsm4(ah[mi], st + 0 * TILE_B + off);
                ldsm4(al[mi], st + 1 * TILE_B + off);
            }
            #pragma unroll
            for (int p = 0; p < 8; p++) {
                int row = p * 16 + b_row_off;
                uint32_t bb[4];
                ldsm4(bb, st + 2 * TILE_B + swz(row, cK));
                #pragma unroll
                for (int mi = 0; mi < 2; mi++) {
                    mma_f16(acc[mi][2 * p],     ah[mi], bb[0], bb[2]);
                    mma_f16(acc[mi][2 * p],     al[mi], bb[0], bb[2]);
                    mma_f16(acc[mi][2 * p + 1], ah[mi], bb[1], bb[3]);
                    mma_f16(acc[mi][2 * p + 1], al[mi], bb[1], bb[3]);
                }
            }
        }
    }

    // ---- epilogue: score row sums ----
    const int tc = (lane & 3) * 2;
    #pragma unroll
    for (int mi = 0; mi < 2; mi++) {
        float s0 = 0.f, s1 = 0.f;
        #pragma unroll
        for (int nf = 0; nf < 16; nf++) {
            int n = nf * 8 + tc;
            float w0 = Ws[n], w1 = Ws[n + 1];
            float v0 = Vs[n], v1 = Vs[n + 1];
            s0 += v0 * tanhf(w0 + acc[mi][nf][0]) + v1 * tanhf(w1 + acc[mi][nf][1]);
            s1 += v0 * tanhf(w0 + acc[mi][nf][2]) + v1 * tanhf(w1 + acc[mi][nf][3]);
        }
        s0 += __shfl_xor_sync(0xffffffffu, s0, 1);
        s0 += __shfl_xor_sync(0xffffffffu, s0, 2);
        s1 += __shfl_xor_sync(0xffffffffu, s1, 1);
        s1 += __shfl_xor_sync(0xffffffffu, s1, 2);
        if ((lane & 3) == 0) {
            int r = mtile * 128 + wm * 32 + mi * 16 + (lane >> 2);
            g_score_part[(size_t)r * NBLK + nt]       = s0;
            g_score_part[(size_t)(r + 8) * NBLK + nt] = s1;
        }
    }
}

// ---------------------------------------------------------------------------
// Softmax (sums NBLK partials + V_b), writes weights.
// ---------------------------------------------------------------------------
__global__ void softmax_kernel(float* __restrict__ weights_out,
                               const float* __restrict__ V_b) {
    __shared__ float red[1024];
    const int b = blockIdx.x, t = threadIdx.x;
    const float vb = V_b[0];

    float sc[4];
    float mx = -1e30f;
    #pragma unroll
    for (int j = 0; j < 4; j++) {
        int s = t + j * 1024;
        const float* p = &g_score_part[(size_t)(b * SEQ + s) * NBLK];
        float v = vb;
        #pragma unroll
        for (int q = 0; q < NBLK; q++) v += p[q];
        sc[j] = v;
        mx = fmaxf(mx, v);
    }
    red[t] = mx;
    __syncthreads();
    for (int o = 512; o > 0; o >>= 1) {
        if (t < o) red[t] = fmaxf(red[t], red[t + o]);
        __syncthreads();
    }
    mx = red[0];
    __syncthreads();

    float e[4], sum = 0.f;
    #pragma unroll
    for (int j = 0; j < 4; j++) { e[j] = expf(sc[j] - mx); sum += e[j]; }
    red[t] = sum;
    __syncthreads();
    for (int o = 512; o > 0; o >>= 1) {
        if (t < o) red[t] += red[t + o];
        __syncthreads();
    }
    float inv = 1.f / red[0];
    #pragma unroll
    for (int j = 0; j < 4; j++)
        weights_out[b * SEQ + t + j * 1024] = e[j] * inv;
}

// ---------------------------------------------------------------------------
// Context
// ---------------------------------------------------------------------------
__global__ void ctx_partial_kernel(const float* __restrict__ H,
                                   const float* __restrict__ W) {
    const int b = blockIdx.x, cs = blockIdx.y, u = threadIdx.x;
    const float* w = W + b * SEQ + cs * 512;
    const float* h = H + ((size_t)b * SEQ + cs * 512) * UNITS + u;
    float a0 = 0.f, a1 = 0.f, a2 = 0.f, a3 = 0.f;
    for (int s = 0; s < 512; s += 4) {
        a0 += w[s + 0] * h[(size_t)(s + 0) * UNITS];
        a1 += w[s + 1] * h[(size_t)(s + 1) * UNITS];
        a2 += w[s + 2] * h[(size_t)(s + 2) * UNITS];
        a3 += w[s + 3] * h[(size_t)(s + 3) * UNITS];
    }
    g_ctx_part[(b * 8 + cs) * UNITS + u] = (a0 + a1) + (a2 + a3);
}

__global__ void ctx_reduce_kernel(float* __restrict__ ctx_out) {
    const int b = blockIdx.x, u = threadIdx.x;
    float acc = 0.f;
    #pragma unroll
    for (int cs = 0; cs < 8; cs++)
        acc += g_ctx_part[(b * 8 + cs) * UNITS + u];
    ctx_out[b * UNITS + u] = acc;
}

// ---------------------------------------------------------------------------
extern "C" void kernel_launch(void* const* d_in, const int* in_sizes, int n_in,
                              void* d_out, int out_size) {
    const float* s_prev = (const float*)d_in[0];
    const float* hidden = (const float*)d_in[1];
    const float* W_w    = (const float*)d_in[2];
    const float* W_b    = (const float*)d_in[3];
    const float* U_w    = (const float*)d_in[4];
    const float* U_b    = (const float*)d_in[5];
    const float* V_w    = (const float*)d_in[6];
    const float* V_b    = (const float*)d_in[7];

    float* out     = (float*)d_out;
    float* ctx_out = out;                      // [32,1024]
    float* w_out   = out + BATCH * UNITS;      // [32,4096,1]

    cudaFuncSetAttribute(score_gemm_mma,
        cudaFuncAttributeMaxDynamicSharedMemorySize, SMEM_GEMM);

    convA_kernel<<<(unsigned)((size_t)M_TOTAL * UNITS / 2048), 256>>>(hidden);
    convB_kernel<<<dim3(32, 32), dim3(32, 32)>>>(U_w);
    ws_kernel<<<BATCH, UNITS>>>(s_prev, W_w, W_b, U_b);
    score_gemm_mma<<<dim3(NBLK, M_TOTAL / 128), 128, SMEM_GEMM>>>(V_w);
    softmax_kernel<<<BATCH, 1024>>>(w_out, V_b);
    ctx_partial_kernel<<<dim3(BATCH, 8), 1024>>>(hidden, w_out);
    ctx_reduce_kernel<<<BATCH, 1024>>>(ctx_out);
}

// round 7
// speedup vs baseline: 3.9067x; 1.1415x over previous
#include <cuda_runtime.h>
#include <cuda_fp16.h>
#include <cstdint>
#include <math.h>

#define BATCH 32
#define SEQ   4096
#define UNITS 1024
#define M_TOTAL (BATCH * SEQ)      // 131072
#define NBLK  8
#define KC    32
#define NCHUNK 32
#define STAGES 4
#define TILE_B 8192                // 128 rows x 64 bytes (fp16, 32 k)
#define STAGE_B (2 * TILE_B)       // Ah, Bh tiles
#define SMEM_GEMM (STAGES * STAGE_B + 2048)   // + Ws(512) + Vs(512) + sc_s(1024)

// ---------------------------------------------------------------------------
// Scratch
// ---------------------------------------------------------------------------
__device__ __half g_Ah[(size_t)M_TOTAL * UNITS];
__device__ __half g_Bh[(size_t)UNITS * UNITS];     // U_w^T [n][k] fp16
__device__ float g_wsb[BATCH * UNITS];
__device__ float g_score_part[(size_t)M_TOTAL * NBLK];
__device__ float g_ctx_part[BATCH * 8 * UNITS];

// ---------------------------------------------------------------------------
// PTX helpers
// ---------------------------------------------------------------------------
__device__ __forceinline__ uint32_t smem_u32(const void* p) {
    uint32_t a;
    asm("{ .reg .u64 t; cvta.to.shared.u64 t, %1; cvt.u32.u64 %0, t; }" : "=r"(a) : "l"(p));
    return a;
}
__device__ __forceinline__ void cp16(uint32_t dst, const void* src) {
    asm volatile("cp.async.cg.shared.global [%0], [%1], 16;"
                 :: "r"(dst), "l"(__cvta_generic_to_global(src)) : "memory");
}
#define CP_COMMIT() asm volatile("cp.async.commit_group;" ::: "memory")
#define CP_WAIT(n)  asm volatile("cp.async.wait_group %0;" :: "n"(n) : "memory")

__device__ __forceinline__ void ldsm4(uint32_t r[4], uint32_t addr) {
    asm volatile("ldmatrix.sync.aligned.m8n8.x4.shared.b16 {%0,%1,%2,%3}, [%4];"
                 : "=r"(r[0]), "=r"(r[1]), "=r"(r[2]), "=r"(r[3]) : "r"(addr));
}
__device__ __forceinline__ void mma_f16(float c[4], const uint32_t a[4],
                                        uint32_t b0, uint32_t b1) {
    asm volatile(
        "mma.sync.aligned.m16n8k16.row.col.f32.f16.f16.f32 "
        "{%0,%1,%2,%3}, {%4,%5,%6,%7}, {%8,%9}, {%0,%1,%2,%3};"
        : "+f"(c[0]), "+f"(c[1]), "+f"(c[2]), "+f"(c[3])
        : "r"(a[0]), "r"(a[1]), "r"(a[2]), "r"(a[3]), "r"(b0), "r"(b1));
}

// swizzled smem offset (bytes) for (row, 16B-chunk c) in a 128x64B tile
__device__ __forceinline__ uint32_t swz(int row, int c) {
    return (uint32_t)(row * 64 + ((c ^ ((row >> 1) & 3)) << 4));
}

// ---------------------------------------------------------------------------
// Prep: hidden fp32 -> fp16 (round-to-nearest)
// ---------------------------------------------------------------------------
__global__ void convA_kernel(const float* __restrict__ A) {
    size_t i = ((size_t)blockIdx.x * 256 + threadIdx.x) * 8;
    float4 v0 = *(const float4*)(A + i);
    float4 v1 = *(const float4*)(A + i + 4);
    __half h[8];
    float f[8] = {v0.x, v0.y, v0.z, v0.w, v1.x, v1.y, v1.z, v1.w};
    #pragma unroll
    for (int q = 0; q < 8; q++) h[q] = __float2half_rn(f[q]);
    *(uint4*)(g_Ah + i) = *(uint4*)h;
}

// ---------------------------------------------------------------------------
// Prep: U_w [k][n] fp32 -> transposed fp16 [n][k]
// ---------------------------------------------------------------------------
__global__ void convB_kernel(const float* __restrict__ U) {
    __shared__ float t[32][33];
    int n0 = blockIdx.x * 32, k0 = blockIdx.y * 32;
    t[threadIdx.y][threadIdx.x] = U[(size_t)(k0 + threadIdx.y) * UNITS + n0 + threadIdx.x];
    __syncthreads();
    float v = t[threadIdx.x][threadIdx.y];
    g_Bh[(size_t)(n0 + threadIdx.y) * UNITS + k0 + threadIdx.x] = __float2half_rn(v);
}

// ---------------------------------------------------------------------------
// Prep: wsb = s_prev@W_w + W_b + U_b
// ---------------------------------------------------------------------------
__global__ void ws_kernel(const float* __restrict__ s_prev,
                          const float* __restrict__ W_w,
                          const float* __restrict__ W_b,
                          const float* __restrict__ U_b) {
    __shared__ float srow[UNITS];
    int b = blockIdx.x, v = threadIdx.x;
    srow[v] = s_prev[b * UNITS + v];
    __syncthreads();
    float a0 = 0.f, a1 = 0.f, a2 = 0.f, a3 = 0.f;
    #pragma unroll 4
    for (int k = 0; k < UNITS; k += 4) {
        a0 += srow[k + 0] * W_w[(size_t)(k + 0) * UNITS + v];
        a1 += srow[k + 1] * W_w[(size_t)(k + 1) * UNITS + v];
        a2 += srow[k + 2] * W_w[(size_t)(k + 2) * UNITS + v];
        a3 += srow[k + 3] * W_w[(size_t)(k + 3) * UNITS + v];
    }
    g_wsb[b * UNITS + v] = (a0 + a1) + (a2 + a3) + W_b[v] + U_b[v];
}

// ---------------------------------------------------------------------------
// GEMM: 128x128 CTA tile, 4 warps (2m x 2n), warp tile 64x64.
// Single-term fp16, 4-stage cp.async, ldmatrix, tanh·V epilogue.
// grid = (NBLK, 1024), block = 128.
// ---------------------------------------------------------------------------
__device__ __forceinline__ void issue_stage(uint32_t sbase, int slot,
                                            int mtile, int nt, int kc, int tid) {
    const uint32_t sb = sbase + slot * STAGE_B;
    const __half* srcA = g_Ah + (size_t)mtile * 128 * UNITS + kc * KC;
    const __half* srcB = g_Bh + (size_t)nt    * 128 * UNITS + kc * KC;
    #pragma unroll
    for (int j = 0; j < 4; j++) {
        int s   = tid + j * 128;
        int row = s >> 2;
        int c   = s & 3;
        uint32_t off = swz(row, c);
        size_t goff  = (size_t)row * UNITS + c * 8;
        cp16(sb + off,          srcA + goff);
        cp16(sb + TILE_B + off, srcB + goff);
    }
}

__global__ __launch_bounds__(128)
void score_gemm_mma(const float* __restrict__ V) {
    extern __shared__ char smem[];
    float* Ws   = (float*)(smem + STAGES * STAGE_B);       // [128]  512 B
    float* Vs   = Ws + 128;                                 // [128]  512 B
    float (*sc_s)[2] = (float(*)[2])(Vs + 128);             // [128][2] 1024 B

    const int nt    = blockIdx.x;
    const int mtile = blockIdx.y;
    const int tid   = threadIdx.x;
    const int lane  = tid & 31;
    const int wid   = tid >> 5;
    const int wm    = wid & 1;           // m half (64 rows)
    const int wn    = wid >> 1;          // n half (64 cols)
    const int b     = mtile >> 5;
    const uint32_t sbase = smem_u32(smem);

    Ws[tid] = g_wsb[b * UNITS + nt * 128 + tid];
    Vs[tid] = V[nt * 128 + tid];

    float acc[4][8][4];
    #pragma unroll
    for (int mi = 0; mi < 4; mi++)
        #pragma unroll
        for (int nf = 0; nf < 8; nf++)
            #pragma unroll
            for (int q = 0; q < 4; q++)
                acc[mi][nf][q] = 0.f;

    // ldmatrix lane geometry
    const int a_row_off = ((lane >> 3) & 1) * 8 + (lane & 7);
    const int k_half    = (lane >> 4) * 8;                   // 0 or 8
    const int b_row_off = lane & 15;

    // prologue: 3 stages in flight
    issue_stage(sbase, 0, mtile, nt, 0, tid); CP_COMMIT();
    issue_stage(sbase, 1, mtile, nt, 1, tid); CP_COMMIT();
    issue_stage(sbase, 2, mtile, nt, 2, tid); CP_COMMIT();

    for (int kc = 0; kc < NCHUNK; kc++) {
        CP_WAIT(2);
        __syncthreads();
        if (kc + 3 < NCHUNK)
            issue_stage(sbase, (kc + 3) & 3, mtile, nt, kc + 3, tid);
        CP_COMMIT();   // empty group at tail keeps wait() bookkeeping uniform

        const uint32_t st = sbase + (kc & 3) * STAGE_B;
        #pragma unroll
        for (int ks = 0; ks < 2; ks++) {
            const int cK = (ks * 16 + k_half) >> 3;
            uint32_t a[4][4];
            #pragma unroll
            for (int mi = 0; mi < 4; mi++) {
                int row = wm * 64 + mi * 16 + a_row_off;
                ldsm4(a[mi], st + swz(row, cK));
            }
            #pragma unroll
            for (int p = 0; p < 4; p++) {
                int row = wn * 64 + p * 16 + b_row_off;
                uint32_t bb[4];
                ldsm4(bb, st + TILE_B + swz(row, cK));
                #pragma unroll
                for (int mi = 0; mi < 4; mi++) {
                    mma_f16(acc[mi][2 * p],     a[mi], bb[0], bb[2]);
                    mma_f16(acc[mi][2 * p + 1], a[mi], bb[1], bb[3]);
                }
            }
        }
    }

    // ---- epilogue: per-warp 64-col partial score, cross-warp combine ----
    const int tc = (lane & 3) * 2;
    #pragma unroll
    for (int mi = 0; mi < 4; mi++) {
        float s0 = 0.f, s1 = 0.f;
        #pragma unroll
        for (int nf = 0; nf < 8; nf++) {
            int n = wn * 64 + nf * 8 + tc;
            float w0 = Ws[n], w1 = Ws[n + 1];
            float v0 = Vs[n], v1 = Vs[n + 1];
            s0 += v0 * tanhf(w0 + acc[mi][nf][0]) + v1 * tanhf(w1 + acc[mi][nf][1]);
            s1 += v0 * tanhf(w0 + acc[mi][nf][2]) + v1 * tanhf(w1 + acc[mi][nf][3]);
        }
        s0 += __shfl_xor_sync(0xffffffffu, s0, 1);
        s0 += __shfl_xor_sync(0xffffffffu, s0, 2);
        s1 += __shfl_xor_sync(0xffffffffu, s1, 1);
        s1 += __shfl_xor_sync(0xffffffffu, s1, 2);
        if ((lane & 3) == 0) {
            int r = wm * 64 + mi * 16 + (lane >> 2);
            sc_s[r][wn]     = s0;
            sc_s[r + 8][wn] = s1;
        }
    }
    __syncthreads();
    g_score_part[((size_t)mtile * 128 + tid) * NBLK + nt] = sc_s[tid][0] + sc_s[tid][1];
}

// ---------------------------------------------------------------------------
// Softmax (sums NBLK partials + V_b), writes weights.
// ---------------------------------------------------------------------------
__global__ void softmax_kernel(float* __restrict__ weights_out,
                               const float* __restrict__ V_b) {
    __shared__ float red[1024];
    const int b = blockIdx.x, t = threadIdx.x;
    const float vb = V_b[0];

    float sc[4];
    float mx = -1e30f;
    #pragma unroll
    for (int j = 0; j < 4; j++) {
        int s = t + j * 1024;
        const float* p = &g_score_part[(size_t)(b * SEQ + s) * NBLK];
        float v = vb;
        #pragma unroll
        for (int q = 0; q < NBLK; q++) v += p[q];
        sc[j] = v;
        mx = fmaxf(mx, v);
    }
    red[t] = mx;
    __syncthreads();
    for (int o = 512; o > 0; o >>= 1) {
        if (t < o) red[t] = fmaxf(red[t], red[t + o]);
        __syncthreads();
    }
    mx = red[0];
    __syncthreads();

    float e[4], sum = 0.f;
    #pragma unroll
    for (int j = 0; j < 4; j++) { e[j] = expf(sc[j] - mx); sum += e[j]; }
    red[t] = sum;
    __syncthreads();
    for (int o = 512; o > 0; o >>= 1) {
        if (t < o) red[t] += red[t + o];
        __syncthreads();
    }
    float inv = 1.f / red[0];
    #pragma unroll
    for (int j = 0; j < 4; j++)
        weights_out[b * SEQ + t + j * 1024] = e[j] * inv;
}

// ---------------------------------------------------------------------------
// Context
// ---------------------------------------------------------------------------
__global__ void ctx_partial_kernel(const float* __restrict__ H,
                                   const float* __restrict__ W) {
    const int b = blockIdx.x, cs = blockIdx.y, u = threadIdx.x;
    const float* w = W + b * SEQ + cs * 512;
    const float* h = H + ((size_t)b * SEQ + cs * 512) * UNITS + u;
    float a0 = 0.f, a1 = 0.f, a2 = 0.f, a3 = 0.f;
    for (int s = 0; s < 512; s += 4) {
        a0 += w[s + 0] * h[(size_t)(s + 0) * UNITS];
        a1 += w[s + 1] * h[(size_t)(s + 1) * UNITS];
        a2 += w[s + 2] * h[(size_t)(s + 2) * UNITS];
        a3 += w[s + 3] * h[(size_t)(s + 3) * UNITS];
    }
    g_ctx_part[(b * 8 + cs) * UNITS + u] = (a0 + a1) + (a2 + a3);
}

__global__ void ctx_reduce_kernel(float* __restrict__ ctx_out) {
    const int b = blockIdx.x, u = threadIdx.x;
    float acc = 0.f;
    #pragma unroll
    for (int cs = 0; cs < 8; cs++)
        acc += g_ctx_part[(b * 8 + cs) * UNITS + u];
    ctx_out[b * UNITS + u] = acc;
}

// ---------------------------------------------------------------------------
extern "C" void kernel_launch(void* const* d_in, const int* in_sizes, int n_in,
                              void* d_out, int out_size) {
    const float* s_prev = (const float*)d_in[0];
    const float* hidden = (const float*)d_in[1];
    const float* W_w    = (const float*)d_in[2];
    const float* W_b    = (const float*)d_in[3];
    const float* U_w    = (const float*)d_in[4];
    const float* U_b    = (const float*)d_in[5];
    const float* V_w    = (const float*)d_in[6];
    const float* V_b    = (const float*)d_in[7];

    float* out     = (float*)d_out;
    float* ctx_out = out;                      // [32,1024]
    float* w_out   = out + BATCH * UNITS;      // [32,4096,1]

    cudaFuncSetAttribute(score_gemm_mma,
        cudaFuncAttributeMaxDynamicSharedMemorySize, SMEM_GEMM);

    convA_kernel<<<(unsigned)((size_t)M_TOTAL * UNITS / 2048), 256>>>(hidden);
    convB_kernel<<<dim3(32, 32), dim3(32, 32)>>>(U_w);
    ws_kernel<<<BATCH, UNITS>>>(s_prev, W_w, W_b, U_b);
    score_gemm_mma<<<dim3(NBLK, M_TOTAL / 128), 128, SMEM_GEMM>>>(V_w);
    softmax_kernel<<<BATCH, 1024>>>(w_out, V_b);
    ctx_partial_kernel<<<dim3(BATCH, 8), 1024>>>(hidden, w_out);
    ctx_reduce_kernel<<<BATCH, 1024>>>(ctx_out);
}

// round 8
// speedup vs baseline: 6.1967x; 1.5862x over previous
#include <cuda_runtime.h>
#include <cuda_fp16.h>
#include <cstdint>
#include <math.h>

#define BATCH 32
#define SEQ   4096
#define UNITS 1024
#define M_TOTAL (BATCH * SEQ)      // 131072
#define NBLK  8
#define KC    32
#define NCHUNK 32
#define STAGES 4
#define TILE_B 8192                // 128 rows x 64 bytes (fp16, 32 k)
#define STAGE_B (2 * TILE_B)       // Ah, Bh tiles
#define SMEM_GEMM (STAGES * STAGE_B + 2048)

// ---------------------------------------------------------------------------
// Scratch
// ---------------------------------------------------------------------------
__device__ __half g_Ah[(size_t)M_TOTAL * UNITS];
__device__ __half g_Bh[(size_t)UNITS * UNITS];     // U_w^T [n][k] fp16
__device__ float g_wsb[BATCH * UNITS];
__device__ float g_score_part[(size_t)M_TOTAL * NBLK];
__device__ float g_ctx_part[BATCH * 8 * UNITS];

// ---------------------------------------------------------------------------
// PTX helpers
// ---------------------------------------------------------------------------
__device__ __forceinline__ uint32_t smem_u32(const void* p) {
    uint32_t a;
    asm("{ .reg .u64 t; cvta.to.shared.u64 t, %1; cvt.u32.u64 %0, t; }" : "=r"(a) : "l"(p));
    return a;
}
__device__ __forceinline__ void cp16(uint32_t dst, const void* src) {
    asm volatile("cp.async.cg.shared.global [%0], [%1], 16;"
                 :: "r"(dst), "l"(__cvta_generic_to_global(src)) : "memory");
}
#define CP_COMMIT() asm volatile("cp.async.commit_group;" ::: "memory")
#define CP_WAIT(n)  asm volatile("cp.async.wait_group %0;" :: "n"(n) : "memory")

__device__ __forceinline__ void ldsm4(uint32_t r[4], uint32_t addr) {
    asm volatile("ldmatrix.sync.aligned.m8n8.x4.shared.b16 {%0,%1,%2,%3}, [%4];"
                 : "=r"(r[0]), "=r"(r[1]), "=r"(r[2]), "=r"(r[3]) : "r"(addr));
}
__device__ __forceinline__ void mma_f16(float c[4], const uint32_t a[4],
                                        uint32_t b0, uint32_t b1) {
    asm volatile(
        "mma.sync.aligned.m16n8k16.row.col.f32.f16.f16.f32 "
        "{%0,%1,%2,%3}, {%4,%5,%6,%7}, {%8,%9}, {%0,%1,%2,%3};"
        : "+f"(c[0]), "+f"(c[1]), "+f"(c[2]), "+f"(c[3])
        : "r"(a[0]), "r"(a[1]), "r"(a[2]), "r"(a[3]), "r"(b0), "r"(b1));
}

// swizzled smem offset (bytes) for (row, 16B-chunk c) in a 128x64B tile
__device__ __forceinline__ uint32_t swz(int row, int c) {
    return (uint32_t)(row * 64 + ((c ^ ((row >> 1) & 3)) << 4));
}

// fast tanh: 1 - 2/(exp(2x)+1)   (MUFU.EX2 + MUFU.RCP path, ~1e-6 rel err)
__device__ __forceinline__ float ftanh(float x) {
    float e2 = __expf(2.f * x);
    return 1.f - __fdividef(2.f, e2 + 1.f);
}

// ---------------------------------------------------------------------------
// Prep: hidden fp32 -> fp16
// ---------------------------------------------------------------------------
__global__ void convA_kernel(const float* __restrict__ A) {
    size_t i = ((size_t)blockIdx.x * 256 + threadIdx.x) * 8;
    float4 v0 = *(const float4*)(A + i);
    float4 v1 = *(const float4*)(A + i + 4);
    __half h[8];
    float f[8] = {v0.x, v0.y, v0.z, v0.w, v1.x, v1.y, v1.z, v1.w};
    #pragma unroll
    for (int q = 0; q < 8; q++) h[q] = __float2half_rn(f[q]);
    *(uint4*)(g_Ah + i) = *(uint4*)h;
}

// ---------------------------------------------------------------------------
// Prep: U_w [k][n] fp32 -> transposed fp16 [n][k]
// ---------------------------------------------------------------------------
__global__ void convB_kernel(const float* __restrict__ U) {
    __shared__ float t[32][33];
    int n0 = blockIdx.x * 32, k0 = blockIdx.y * 32;
    t[threadIdx.y][threadIdx.x] = U[(size_t)(k0 + threadIdx.y) * UNITS + n0 + threadIdx.x];
    __syncthreads();
    float v = t[threadIdx.x][threadIdx.y];
    g_Bh[(size_t)(n0 + threadIdx.y) * UNITS + k0 + threadIdx.x] = __float2half_rn(v);
}

// ---------------------------------------------------------------------------
// Prep: wsb = s_prev@W_w + W_b + U_b
// ---------------------------------------------------------------------------
__global__ void ws_kernel(const float* __restrict__ s_prev,
                          const float* __restrict__ W_w,
                          const float* __restrict__ W_b,
                          const float* __restrict__ U_b) {
    __shared__ float srow[UNITS];
    int b = blockIdx.x, v = threadIdx.x;
    srow[v] = s_prev[b * UNITS + v];
    __syncthreads();
    float a0 = 0.f, a1 = 0.f, a2 = 0.f, a3 = 0.f;
    #pragma unroll 4
    for (int k = 0; k < UNITS; k += 4) {
        a0 += srow[k + 0] * W_w[(size_t)(k + 0) * UNITS + v];
        a1 += srow[k + 1] * W_w[(size_t)(k + 1) * UNITS + v];
        a2 += srow[k + 2] * W_w[(size_t)(k + 2) * UNITS + v];
        a3 += srow[k + 3] * W_w[(size_t)(k + 3) * UNITS + v];
    }
    g_wsb[b * UNITS + v] = (a0 + a1) + (a2 + a3) + W_b[v] + U_b[v];
}

// ---------------------------------------------------------------------------
// GEMM: 128x128 CTA tile, 8 warps (4m x 2n), warp tile 32x64.
// Single-term fp16, 4-stage cp.async, ldmatrix, fast-tanh·V epilogue.
// grid = (NBLK, 1024), block = 256, 2 CTAs/SM (16 warps).
// ---------------------------------------------------------------------------
__global__ __launch_bounds__(256, 2)
void score_gemm_mma(const float* __restrict__ V) {
    extern __shared__ char smem[];
    float* Ws = (float*)(smem + STAGES * STAGE_B);   // [128]
    float* Vs = Ws + 128;                             // [128]
    float (*sc_s)[2] = (float(*)[2])(Vs + 128);       // [128][2]

    const int nt    = blockIdx.x;
    const int mtile = blockIdx.y;
    const int tid   = threadIdx.x;
    const int lane  = tid & 31;
    const int wid   = tid >> 5;
    const int wm    = wid & 3;           // m quarter (32 rows)
    const int wn    = wid >> 2;          // n half (64 cols)
    const int b     = mtile >> 5;
    const uint32_t sbase = smem_u32(smem);

    if (tid < 128) {
        Ws[tid] = g_wsb[b * UNITS + nt * 128 + tid];
        Vs[tid] = V[nt * 128 + tid];
    }

    float acc[2][8][4];
    #pragma unroll
    for (int mi = 0; mi < 2; mi++)
        #pragma unroll
        for (int nf = 0; nf < 8; nf++)
            #pragma unroll
            for (int q = 0; q < 4; q++)
                acc[mi][nf][q] = 0.f;

    // --- hoisted cp.async geometry: 2 segments per tile per thread ---
    // s = tid + j*256, row = s>>2, c = s&3
    uint32_t cp_off[2];
    const __half* cp_srcA[2];
    const __half* cp_srcB[2];
    {
        const __half* baseA = g_Ah + (size_t)mtile * 128 * UNITS;
        const __half* baseB = g_Bh + (size_t)nt    * 128 * UNITS;
        #pragma unroll
        for (int j = 0; j < 2; j++) {
            int s = tid + j * 256;
            int row = s >> 2, c = s & 3;
            cp_off[j]  = swz(row, c);
            cp_srcA[j] = baseA + (size_t)row * UNITS + c * 8;
            cp_srcB[j] = baseB + (size_t)row * UNITS + c * 8;
        }
    }

    // --- hoisted ldsm offsets ---
    const int a_row_off = ((lane >> 3) & 1) * 8 + (lane & 7);
    const int k_sub     = (lane >> 4);                 // 0/1 -> chunk +0/+1
    const int b_row_off = lane & 15;
    uint32_t offA[2][2], offB[2][4];                   // [ks][mi] / [ks][p]
    #pragma unroll
    for (int ks = 0; ks < 2; ks++) {
        int cK = ks * 2 + k_sub;
        #pragma unroll
        for (int mi = 0; mi < 2; mi++)
            offA[ks][mi] = swz(wm * 32 + mi * 16 + a_row_off, cK);
        #pragma unroll
        for (int p = 0; p < 4; p++)
            offB[ks][p] = TILE_B + swz(wn * 64 + p * 16 + b_row_off, cK);
    }

    // prologue: 3 stages in flight
    #pragma unroll
    for (int st0 = 0; st0 < 3; st0++) {
        uint32_t sb = sbase + st0 * STAGE_B;
        #pragma unroll
        for (int j = 0; j < 2; j++) {
            cp16(sb + cp_off[j],          cp_srcA[j] + st0 * KC);
            cp16(sb + TILE_B + cp_off[j], cp_srcB[j] + st0 * KC);
        }
        CP_COMMIT();
    }

    for (int kc = 0; kc < NCHUNK; kc++) {
        CP_WAIT(2);
        __syncthreads();
        if (kc + 3 < NCHUNK) {
            uint32_t sb = sbase + ((kc + 3) & 3) * STAGE_B;
            #pragma unroll
            for (int j = 0; j < 2; j++) {
                cp16(sb + cp_off[j],          cp_srcA[j] + (kc + 3) * KC);
                cp16(sb + TILE_B + cp_off[j], cp_srcB[j] + (kc + 3) * KC);
            }
        }
        CP_COMMIT();

        const uint32_t st = sbase + (kc & 3) * STAGE_B;
        #pragma unroll
        for (int ks = 0; ks < 2; ks++) {
            uint32_t a[2][4];
            #pragma unroll
            for (int mi = 0; mi < 2; mi++)
                ldsm4(a[mi], st + offA[ks][mi]);
            #pragma unroll
            for (int p = 0; p < 4; p++) {
                uint32_t bb[4];
                ldsm4(bb, st + offB[ks][p]);
                #pragma unroll
                for (int mi = 0; mi < 2; mi++) {
                    mma_f16(acc[mi][2 * p],     a[mi], bb[0], bb[2]);
                    mma_f16(acc[mi][2 * p + 1], a[mi], bb[1], bb[3]);
                }
            }
        }
    }

    // ---- epilogue: per-warp 64-col partial score, cross-warp combine ----
    const int tc = (lane & 3) * 2;
    #pragma unroll
    for (int mi = 0; mi < 2; mi++) {
        float s0 = 0.f, s1 = 0.f;
        #pragma unroll
        for (int nf = 0; nf < 8; nf++) {
            int n = wn * 64 + nf * 8 + tc;
            float w0 = Ws[n], w1 = Ws[n + 1];
            float v0 = Vs[n], v1 = Vs[n + 1];
            s0 += v0 * ftanh(w0 + acc[mi][nf][0]) + v1 * ftanh(w1 + acc[mi][nf][1]);
            s1 += v0 * ftanh(w0 + acc[mi][nf][2]) + v1 * ftanh(w1 + acc[mi][nf][3]);
        }
        s0 += __shfl_xor_sync(0xffffffffu, s0, 1);
        s0 += __shfl_xor_sync(0xffffffffu, s0, 2);
        s1 += __shfl_xor_sync(0xffffffffu, s1, 1);
        s1 += __shfl_xor_sync(0xffffffffu, s1, 2);
        if ((lane & 3) == 0) {
            int r = wm * 32 + mi * 16 + (lane >> 2);
            sc_s[r][wn]     = s0;
            sc_s[r + 8][wn] = s1;
        }
    }
    __syncthreads();
    if (tid < 128)
        g_score_part[((size_t)mtile * 128 + tid) * NBLK + nt] =
            sc_s[tid][0] + sc_s[tid][1];
}

// ---------------------------------------------------------------------------
// Softmax (sums NBLK partials + V_b), writes weights.
// ---------------------------------------------------------------------------
__global__ void softmax_kernel(float* __restrict__ weights_out,
                               const float* __restrict__ V_b) {
    __shared__ float red[1024];
    const int b = blockIdx.x, t = threadIdx.x;
    const float vb = V_b[0];

    float sc[4];
    float mx = -1e30f;
    #pragma unroll
    for (int j = 0; j < 4; j++) {
        int s = t + j * 1024;
        const float* p = &g_score_part[(size_t)(b * SEQ + s) * NBLK];
        float v = vb;
        #pragma unroll
        for (int q = 0; q < NBLK; q++) v += p[q];
        sc[j] = v;
        mx = fmaxf(mx, v);
    }
    red[t] = mx;
    __syncthreads();
    for (int o = 512; o > 0; o >>= 1) {
        if (t < o) red[t] = fmaxf(red[t], red[t + o]);
        __syncthreads();
    }
    mx = red[0];
    __syncthreads();

    float e[4], sum = 0.f;
    #pragma unroll
    for (int j = 0; j < 4; j++) { e[j] = expf(sc[j] - mx); sum += e[j]; }
    red[t] = sum;
    __syncthreads();
    for (int o = 512; o > 0; o >>= 1) {
        if (t < o) red[t] += red[t + o];
        __syncthreads();
    }
    float inv = 1.f / red[0];
    #pragma unroll
    for (int j = 0; j < 4; j++)
        weights_out[b * SEQ + t + j * 1024] = e[j] * inv;
}

// ---------------------------------------------------------------------------
// Context
// ---------------------------------------------------------------------------
__global__ void ctx_partial_kernel(const float* __restrict__ H,
                                   const float* __restrict__ W) {
    const int b = blockIdx.x, cs = blockIdx.y, u = threadIdx.x;
    const float* w = W + b * SEQ + cs * 512;
    const float* h = H + ((size_t)b * SEQ + cs * 512) * UNITS + u;
    float a0 = 0.f, a1 = 0.f, a2 = 0.f, a3 = 0.f;
    for (int s = 0; s < 512; s += 4) {
        a0 += w[s + 0] * h[(size_t)(s + 0) * UNITS];
        a1 += w[s + 1] * h[(size_t)(s + 1) * UNITS];
        a2 += w[s + 2] * h[(size_t)(s + 2) * UNITS];
        a3 += w[s + 3] * h[(size_t)(s + 3) * UNITS];
    }
    g_ctx_part[(b * 8 + cs) * UNITS + u] = (a0 + a1) + (a2 + a3);
}

__global__ void ctx_reduce_kernel(float* __restrict__ ctx_out) {
    const int b = blockIdx.x, u = threadIdx.x;
    float acc = 0.f;
    #pragma unroll
    for (int cs = 0; cs < 8; cs++)
        acc += g_ctx_part[(b * 8 + cs) * UNITS + u];
    ctx_out[b * UNITS + u] = acc;
}

// ---------------------------------------------------------------------------
extern "C" void kernel_launch(void* const* d_in, const int* in_sizes, int n_in,
                              void* d_out, int out_size) {
    const float* s_prev = (const float*)d_in[0];
    const float* hidden = (const float*)d_in[1];
    const float* W_w    = (const float*)d_in[2];
    const float* W_b    = (const float*)d_in[3];
    const float* U_w    = (const float*)d_in[4];
    const float* U_b    = (const float*)d_in[5];
    const float* V_w    = (const float*)d_in[6];
    const float* V_b    = (const float*)d_in[7];

    float* out     = (float*)d_out;
    float* ctx_out = out;                      // [32,1024]
    float* w_out   = out + BATCH * UNITS;      // [32,4096,1]

    cudaFuncSetAttribute(score_gemm_mma,
        cudaFuncAttributeMaxDynamicSharedMemorySize, SMEM_GEMM);

    convA_kernel<<<(unsigned)((size_t)M_TOTAL * UNITS / 2048), 256>>>(hidden);
    convB_kernel<<<dim3(32, 32), dim3(32, 32)>>>(U_w);
    ws_kernel<<<BATCH, UNITS>>>(s_prev, W_w, W_b, U_b);
    score_gemm_mma<<<dim3(NBLK, M_TOTAL / 128), 256, SMEM_GEMM>>>(V_w);
    softmax_kernel<<<BATCH, 1024>>>(w_out, V_b);
    ctx_partial_kernel<<<dim3(BATCH, 8), 1024>>>(hidden, w_out);
    ctx_reduce_kernel<<<BATCH, 1024>>>(ctx_out);
}

// round 9
// speedup vs baseline: 6.5317x; 1.0541x over previous
#include <cuda_runtime.h>
#include <cuda_fp16.h>
#include <cstdint>
#include <math.h>

#define BATCH 32
#define SEQ   4096
#define UNITS 1024
#define M_TOTAL (BATCH * SEQ)      // 131072
#define NBLK  8
#define KC    64
#define NCHUNK 16
#define STAGES 3
#define TILE_B 16384               // 128 rows x 128 bytes (fp16, 64 k)
#define STAGE_B (2 * TILE_B)       // Ah, Bh tiles
#define SMEM_GEMM (STAGES * STAGE_B + 2048)   // 100352

// ---------------------------------------------------------------------------
// Scratch
// ---------------------------------------------------------------------------
__device__ __half g_Ah[(size_t)M_TOTAL * UNITS];
__device__ __half g_Bh[(size_t)UNITS * UNITS];     // U_w^T [n][k] fp16
__device__ float g_wsb[BATCH * UNITS];
__device__ float g_score_part[(size_t)M_TOTAL * NBLK];
__device__ float g_ctx_part[BATCH * 8 * UNITS];

// ---------------------------------------------------------------------------
// PTX helpers
// ---------------------------------------------------------------------------
__device__ __forceinline__ uint32_t smem_u32(const void* p) {
    uint32_t a;
    asm("{ .reg .u64 t; cvta.to.shared.u64 t, %1; cvt.u32.u64 %0, t; }" : "=r"(a) : "l"(p));
    return a;
}
__device__ __forceinline__ void cp16(uint32_t dst, const void* src) {
    asm volatile("cp.async.cg.shared.global [%0], [%1], 16;"
                 :: "r"(dst), "l"(__cvta_generic_to_global(src)) : "memory");
}
#define CP_COMMIT() asm volatile("cp.async.commit_group;" ::: "memory")
#define CP_WAIT(n)  asm volatile("cp.async.wait_group %0;" :: "n"(n) : "memory")

__device__ __forceinline__ void ldsm4(uint32_t r[4], uint32_t addr) {
    asm volatile("ldmatrix.sync.aligned.m8n8.x4.shared.b16 {%0,%1,%2,%3}, [%4];"
                 : "=r"(r[0]), "=r"(r[1]), "=r"(r[2]), "=r"(r[3]) : "r"(addr));
}
__device__ __forceinline__ void mma_f16(float c[4], const uint32_t a[4],
                                        uint32_t b0, uint32_t b1) {
    asm volatile(
        "mma.sync.aligned.m16n8k16.row.col.f32.f16.f16.f32 "
        "{%0,%1,%2,%3}, {%4,%5,%6,%7}, {%8,%9}, {%0,%1,%2,%3};"
        : "+f"(c[0]), "+f"(c[1]), "+f"(c[2]), "+f"(c[3])
        : "r"(a[0]), "r"(a[1]), "r"(a[2]), "r"(a[3]), "r"(b0), "r"(b1));
}

// SW128 swizzle: 128x128B tile, (row, 16B-chunk c), c in 0..7
__device__ __forceinline__ uint32_t swz128(int row, int c) {
    return (uint32_t)(row * 128 + ((c ^ (row & 7)) << 4));
}

// fast tanh: 1 - 2/(exp(2x)+1)
__device__ __forceinline__ float ftanh(float x) {
    float e2 = __expf(2.f * x);
    return 1.f - __fdividef(2.f, e2 + 1.f);
}

// ---------------------------------------------------------------------------
// Prep: hidden fp32 -> fp16
// ---------------------------------------------------------------------------
__global__ void convA_kernel(const float* __restrict__ A) {
    size_t i = ((size_t)blockIdx.x * 256 + threadIdx.x) * 8;
    float4 v0 = *(const float4*)(A + i);
    float4 v1 = *(const float4*)(A + i + 4);
    __half h[8];
    float f[8] = {v0.x, v0.y, v0.z, v0.w, v1.x, v1.y, v1.z, v1.w};
    #pragma unroll
    for (int q = 0; q < 8; q++) h[q] = __float2half_rn(f[q]);
    *(uint4*)(g_Ah + i) = *(uint4*)h;
}

// ---------------------------------------------------------------------------
// Prep: U_w [k][n] fp32 -> transposed fp16 [n][k]
// ---------------------------------------------------------------------------
__global__ void convB_kernel(const float* __restrict__ U) {
    __shared__ float t[32][33];
    int n0 = blockIdx.x * 32, k0 = blockIdx.y * 32;
    t[threadIdx.y][threadIdx.x] = U[(size_t)(k0 + threadIdx.y) * UNITS + n0 + threadIdx.x];
    __syncthreads();
    float v = t[threadIdx.x][threadIdx.y];
    g_Bh[(size_t)(n0 + threadIdx.y) * UNITS + k0 + threadIdx.x] = __float2half_rn(v);
}

// ---------------------------------------------------------------------------
// Prep: wsb = s_prev@W_w + W_b + U_b
// ---------------------------------------------------------------------------
__global__ void ws_kernel(const float* __restrict__ s_prev,
                          const float* __restrict__ W_w,
                          const float* __restrict__ W_b,
                          const float* __restrict__ U_b) {
    __shared__ float srow[UNITS];
    int b = blockIdx.x, v = threadIdx.x;
    srow[v] = s_prev[b * UNITS + v];
    __syncthreads();
    float a0 = 0.f, a1 = 0.f, a2 = 0.f, a3 = 0.f;
    #pragma unroll 4
    for (int k = 0; k < UNITS; k += 4) {
        a0 += srow[k + 0] * W_w[(size_t)(k + 0) * UNITS + v];
        a1 += srow[k + 1] * W_w[(size_t)(k + 1) * UNITS + v];
        a2 += srow[k + 2] * W_w[(size_t)(k + 2) * UNITS + v];
        a3 += srow[k + 3] * W_w[(size_t)(k + 3) * UNITS + v];
    }
    g_wsb[b * UNITS + v] = (a0 + a1) + (a2 + a3) + W_b[v] + U_b[v];
}

// ---------------------------------------------------------------------------
// GEMM: 128x128 CTA tile, 8 warps (4m x 2n), warp tile 32x64.
// fp16 single-term, KC=64 chunks, 3-stage cp.async, fast-tanh·V epilogue.
// grid = (NBLK, 1024), block = 256, 2 CTAs/SM.
// ---------------------------------------------------------------------------
__global__ __launch_bounds__(256, 2)
void score_gemm_mma(const float* __restrict__ V) {
    extern __shared__ char smem[];
    float* Ws = (float*)(smem + STAGES * STAGE_B);   // [128]
    float* Vs = Ws + 128;                             // [128]
    float (*sc_s)[2] = (float(*)[2])(Vs + 128);       // [128][2]

    const int nt    = blockIdx.x;
    const int mtile = blockIdx.y;
    const int tid   = threadIdx.x;
    const int lane  = tid & 31;
    const int wid   = tid >> 5;
    const int wm    = wid & 3;           // m quarter (32 rows)
    const int wn    = wid >> 2;          // n half (64 cols)
    const int b     = mtile >> 5;
    const uint32_t sbase = smem_u32(smem);

    if (tid < 128) {
        Ws[tid] = g_wsb[b * UNITS + nt * 128 + tid];
        Vs[tid] = V[nt * 128 + tid];
    }

    float acc[2][8][4];
    #pragma unroll
    for (int mi = 0; mi < 2; mi++)
        #pragma unroll
        for (int nf = 0; nf < 8; nf++)
            #pragma unroll
            for (int q = 0; q < 4; q++)
                acc[mi][nf][q] = 0.f;

    // --- cp.async geometry: 4 segments per tile per thread ---
    const __half* baseA = g_Ah + (size_t)mtile * 128 * UNITS;
    const __half* baseB = g_Bh + (size_t)nt    * 128 * UNITS;
    const ptrdiff_t dBA = baseB - baseA;
    uint32_t cp_off[4];
    const __half* cpA[4];
    #pragma unroll
    for (int j = 0; j < 4; j++) {
        int s = tid + j * 256;           // 0..1023
        int row = s >> 3, c = s & 7;
        cp_off[j] = swz128(row, c);
        cpA[j]    = baseA + (size_t)row * UNITS + c * 8;
    }

    // --- ldsm fragment bases ---
    const int a_row_off = ((lane >> 3) & 1) * 8 + (lane & 7);
    const int k_sub     = lane >> 4;          // 0/1
    const int b_row_off = lane & 15;
    uint32_t rbA[2]; int r7A[2];
    #pragma unroll
    for (int mi = 0; mi < 2; mi++) {
        int row = wm * 32 + mi * 16 + a_row_off;
        rbA[mi] = row * 128; r7A[mi] = row & 7;
    }
    uint32_t rbB[4]; int r7B[4];
    #pragma unroll
    for (int p = 0; p < 4; p++) {
        int row = wn * 64 + p * 16 + b_row_off;
        rbB[p] = TILE_B + row * 128; r7B[p] = row & 7;
    }

    // prologue: 2 stages in flight
    #pragma unroll
    for (int st0 = 0; st0 < 2; st0++) {
        uint32_t sb = sbase + st0 * STAGE_B;
        #pragma unroll
        for (int j = 0; j < 4; j++) {
            cp16(sb + cp_off[j],          cpA[j] + st0 * KC);
            cp16(sb + TILE_B + cp_off[j], cpA[j] + dBA + st0 * KC);
        }
        CP_COMMIT();
    }

    int cons = 0, prod = 2;
    for (int kc = 0; kc < NCHUNK; kc++) {
        CP_WAIT(1);
        __syncthreads();
        if (kc + 2 < NCHUNK) {
            uint32_t sb = sbase + prod * STAGE_B;
            #pragma unroll
            for (int j = 0; j < 4; j++) {
                cp16(sb + cp_off[j],          cpA[j] + (kc + 2) * KC);
                cp16(sb + TILE_B + cp_off[j], cpA[j] + dBA + (kc + 2) * KC);
            }
        }
        CP_COMMIT();

        const uint32_t st = sbase + cons * STAGE_B;
        #pragma unroll
        for (int ks = 0; ks < 4; ks++) {
            const int kk = (ks << 1) | k_sub;
            uint32_t a[2][4];
            #pragma unroll
            for (int mi = 0; mi < 2; mi++)
                ldsm4(a[mi], st + rbA[mi] + (uint32_t)((kk ^ r7A[mi]) << 4));
            #pragma unroll
            for (int p = 0; p < 4; p++) {
                uint32_t bb[4];
                ldsm4(bb, st + rbB[p] + (uint32_t)((kk ^ r7B[p]) << 4));
                #pragma unroll
                for (int mi = 0; mi < 2; mi++) {
                    mma_f16(acc[mi][2 * p],     a[mi], bb[0], bb[2]);
                    mma_f16(acc[mi][2 * p + 1], a[mi], bb[1], bb[3]);
                }
            }
        }
        cons = (cons == 2) ? 0 : cons + 1;
        prod = (prod == 2) ? 0 : prod + 1;
    }

    // ---- epilogue ----
    const int tc = (lane & 3) * 2;
    #pragma unroll
    for (int mi = 0; mi < 2; mi++) {
        float s0 = 0.f, s1 = 0.f;
        #pragma unroll
        for (int nf = 0; nf < 8; nf++) {
            int n = wn * 64 + nf * 8 + tc;
            float w0 = Ws[n], w1 = Ws[n + 1];
            float v0 = Vs[n], v1 = Vs[n + 1];
            s0 += v0 * ftanh(w0 + acc[mi][nf][0]) + v1 * ftanh(w1 + acc[mi][nf][1]);
            s1 += v0 * ftanh(w0 + acc[mi][nf][2]) + v1 * ftanh(w1 + acc[mi][nf][3]);
        }
        s0 += __shfl_xor_sync(0xffffffffu, s0, 1);
        s0 += __shfl_xor_sync(0xffffffffu, s0, 2);
        s1 += __shfl_xor_sync(0xffffffffu, s1, 1);
        s1 += __shfl_xor_sync(0xffffffffu, s1, 2);
        if ((lane & 3) == 0) {
            int r = wm * 32 + mi * 16 + (lane >> 2);
            sc_s[r][wn]     = s0;
            sc_s[r + 8][wn] = s1;
        }
    }
    __syncthreads();
    if (tid < 128)
        g_score_part[((size_t)mtile * 128 + tid) * NBLK + nt] =
            sc_s[tid][0] + sc_s[tid][1];
}

// ---------------------------------------------------------------------------
// Softmax (sums NBLK partials + V_b), writes weights.
// ---------------------------------------------------------------------------
__global__ void softmax_kernel(float* __restrict__ weights_out,
                               const float* __restrict__ V_b) {
    __shared__ float red[1024];
    const int b = blockIdx.x, t = threadIdx.x;
    const float vb = V_b[0];

    float sc[4];
    float mx = -1e30f;
    #pragma unroll
    for (int j = 0; j < 4; j++) {
        int s = t + j * 1024;
        const float* p = &g_score_part[(size_t)(b * SEQ + s) * NBLK];
        float v = vb;
        #pragma unroll
        for (int q = 0; q < NBLK; q++) v += p[q];
        sc[j] = v;
        mx = fmaxf(mx, v);
    }
    red[t] = mx;
    __syncthreads();
    for (int o = 512; o > 0; o >>= 1) {
        if (t < o) red[t] = fmaxf(red[t], red[t + o]);
        __syncthreads();
    }
    mx = red[0];
    __syncthreads();

    float e[4], sum = 0.f;
    #pragma unroll
    for (int j = 0; j < 4; j++) { e[j] = expf(sc[j] - mx); sum += e[j]; }
    red[t] = sum;
    __syncthreads();
    for (int o = 512; o > 0; o >>= 1) {
        if (t < o) red[t] += red[t + o];
        __syncthreads();
    }
    float inv = 1.f / red[0];
    #pragma unroll
    for (int j = 0; j < 4; j++)
        weights_out[b * SEQ + t + j * 1024] = e[j] * inv;
}

// ---------------------------------------------------------------------------
// Context: weighted sum over S, reading fp16 g_Ah (halved DRAM traffic).
// ---------------------------------------------------------------------------
__global__ void ctx_partial_kernel(const float* __restrict__ W) {
    const int b = blockIdx.x, cs = blockIdx.y, u = threadIdx.x;
    const float* w = W + b * SEQ + cs * 512;
    const __half* h = g_Ah + ((size_t)b * SEQ + cs * 512) * UNITS + u;
    float a0 = 0.f, a1 = 0.f, a2 = 0.f, a3 = 0.f;
    for (int s = 0; s < 512; s += 4) {
        a0 += w[s + 0] * __half2float(h[(size_t)(s + 0) * UNITS]);
        a1 += w[s + 1] * __half2float(h[(size_t)(s + 1) * UNITS]);
        a2 += w[s + 2] * __half2float(h[(size_t)(s + 2) * UNITS]);
        a3 += w[s + 3] * __half2float(h[(size_t)(s + 3) * UNITS]);
    }
    g_ctx_part[(b * 8 + cs) * UNITS + u] = (a0 + a1) + (a2 + a3);
}

__global__ void ctx_reduce_kernel(float* __restrict__ ctx_out) {
    const int b = blockIdx.x, u = threadIdx.x;
    float acc = 0.f;
    #pragma unroll
    for (int cs = 0; cs < 8; cs++)
        acc += g_ctx_part[(b * 8 + cs) * UNITS + u];
    ctx_out[b * UNITS + u] = acc;
}

// ---------------------------------------------------------------------------
extern "C" void kernel_launch(void* const* d_in, const int* in_sizes, int n_in,
                              void* d_out, int out_size) {
    const float* s_prev = (const float*)d_in[0];
    const float* hidden = (const float*)d_in[1];
    const float* W_w    = (const float*)d_in[2];
    const float* W_b    = (const float*)d_in[3];
    const float* U_w    = (const float*)d_in[4];
    const float* U_b    = (const float*)d_in[5];
    const float* V_w    = (const float*)d_in[6];
    const float* V_b    = (const float*)d_in[7];

    float* out     = (float*)d_out;
    float* ctx_out = out;                      // [32,1024]
    float* w_out   = out + BATCH * UNITS;      // [32,4096,1]

    cudaFuncSetAttribute(score_gemm_mma,
        cudaFuncAttributeMaxDynamicSharedMemorySize, SMEM_GEMM);

    convA_kernel<<<(unsigned)((size_t)M_TOTAL * UNITS / 2048), 256>>>(hidden);
    convB_kernel<<<dim3(32, 32), dim3(32, 32)>>>(U_w);
    ws_kernel<<<BATCH, UNITS>>>(s_prev, W_w, W_b, U_b);
    score_gemm_mma<<<dim3(NBLK, M_TOTAL / 128), 256, SMEM_GEMM>>>(V_w);
    softmax_kernel<<<BATCH, 1024>>>(w_out, V_b);
    ctx_partial_kernel<<<dim3(BATCH, 8), 1024>>>(w_out);
    ctx_reduce_kernel<<<BATCH, 1024>>>(ctx_out);
}